// round 7
// baseline (speedup 1.0000x reference)
#include <cuda_runtime.h>
#include <cstdint>

#define Bdim 2
#define Tdim 2048
#define Edim 1024
#define Hdim 16
#define HD 64
#define QKV3 192
#define KT 16            // keys per tile
#define QTILE 128        // queries per block (4 per 4-lane group, 32 groups)
#define THREADS 128
#define NT (Tdim / KT)   // 128 tiles
#define STAGES 4

// Scratch: Q/K/V in [B, H, T, HD] layout. 16 MB each.
__device__ float g_Q[Bdim * Hdim * Tdim * HD];
__device__ float g_K[Bdim * Hdim * Tdim * HD];
__device__ float g_V[Bdim * Hdim * Tdim * HD];

// ---------------------------------------------------------------------------
// Packed f32x2 helpers (Blackwell FFMA2 — only reachable via PTX).
// ---------------------------------------------------------------------------
typedef unsigned long long ull;

__device__ __forceinline__ ull fma2(ull a, ull b, ull c) {
    ull d;
    asm("fma.rn.f32x2 %0, %1, %2, %3;" : "=l"(d) : "l"(a), "l"(b), "l"(c));
    return d;
}
__device__ __forceinline__ ull mul2(ull a, ull b) {
    ull d;
    asm("mul.rn.f32x2 %0, %1, %2;" : "=l"(d) : "l"(a), "l"(b));
    return d;
}
__device__ __forceinline__ ull pack2(float lo, float hi) {
    ull r;
    asm("mov.b64 %0, {%1, %2};" : "=l"(r) : "f"(lo), "f"(hi));
    return r;
}
__device__ __forceinline__ float hadd2(ull v) {
    float lo, hi;
    asm("mov.b64 {%0, %1}, %2;" : "=f"(lo), "=f"(hi) : "l"(v));
    return lo + hi;
}
__device__ __forceinline__ void unpack2(ull v, float& lo, float& hi) {
    asm("mov.b64 {%0, %1}, %2;" : "=f"(lo), "=f"(hi) : "l"(v));
}

__device__ __forceinline__ void cp_async16(void* smem_dst, const void* gmem_src) {
    uint32_t s = (uint32_t)__cvta_generic_to_shared(smem_dst);
    asm volatile("cp.async.cg.shared.global [%0], [%1], 16;"
                 :: "r"(s), "l"(gmem_src) : "memory");
}
__device__ __forceinline__ void cp_commit() {
    asm volatile("cp.async.commit_group;" ::: "memory");
}
__device__ __forceinline__ void cp_wait2() {
    asm volatile("cp.async.wait_group 2;" ::: "memory");
}

// ---------------------------------------------------------------------------
// Kernel 1: QKV projection (f32x2 inner loop). Unchanged (verified R2).
// ---------------------------------------------------------------------------
__global__ __launch_bounds__(QKV3) void qkv_proj_kernel(
    const float* __restrict__ x,      // [B, T, E]
    const float* __restrict__ W,      // [HD, 3*HD]
    const float* __restrict__ bias)   // [3*HD]
{
    __shared__ __align__(16) float xs[Edim];
    const int bt = blockIdx.x;
    const int b  = bt / Tdim;
    const int t  = bt % Tdim;

    const float* xrow = x + (size_t)bt * Edim;
    for (int i = threadIdx.x; i < Edim; i += QKV3) xs[i] = xrow[i];
    __syncthreads();

    const int d = threadIdx.x;  // 0..191

    ull w2[HD / 2];
#pragma unroll 8
    for (int k2 = 0; k2 < HD / 2; k2++)
        w2[k2] = pack2(W[(2 * k2) * QKV3 + d], W[(2 * k2 + 1) * QKV3 + d]);

    const float bv = bias[d];
    const ull* xs2 = (const ull*)xs;

    float acc[Hdim];
#pragma unroll
    for (int h = 0; h < Hdim; h++) {
        ull a0 = 0ULL, a1 = 0ULL;
#pragma unroll
        for (int k2 = 0; k2 < HD / 2; k2 += 2) {
            a0 = fma2(xs2[h * (HD / 2) + k2],     w2[k2],     a0);
            a1 = fma2(xs2[h * (HD / 2) + k2 + 1], w2[k2 + 1], a1);
        }
        acc[h] = bv + (hadd2(a0) + hadd2(a1));
    }

#pragma unroll
    for (int h = 0; h < Hdim; h++) {
        const size_t off = ((size_t)(b * Hdim + h) * Tdim + t) * HD;
        if (d < HD) {
            g_Q[off + d] = acc[h] * 0.125f;   // 1/sqrt(64) folded into Q
        } else if (d < 2 * HD) {
            g_K[off + d - HD] = acc[h];
        } else {
            g_V[off + d - 2 * HD] = acc[h];
        }
    }
}

// ---------------------------------------------------------------------------
// Kernel 2: flash attention, 4-lane query groups.
// Lanes c=0..3 of a group cooperate on queries qbase+0..3. Lane c owns
// head-dim vecs {4u+c}. Slot X on lane c = query (qbase + (c^X)), so all
// cross-lane exchanges are xor-shuffles with compile-time slot indices.
// Each K/V smem vector is read ONCE and serves 4 queries.
// ---------------------------------------------------------------------------
#define ROW_V2  (HD / 4)              // ulonglong2 per key row = 16
#define TILE_V2 (KT * ROW_V2)         // ulonglong2 per tile per array = 256

__global__ __launch_bounds__(THREADS, 1) void attn_kernel(float* __restrict__ out)
{
    // 4-stage cp.async pipeline: 2 arrays * 4 stages * 256 * 16B = 32 KB
    __shared__ __align__(16) ulonglong2 Ks[STAGES][TILE_V2];
    __shared__ __align__(16) ulonglong2 Vs[STAGES][TILE_V2];

    const int bh = blockIdx.y;
    const int b  = bh >> 4;           // H = 16
    const int h  = bh & 15;
    const int gi = threadIdx.x >> 2;  // group index 0..31
    const int c  = threadIdx.x & 3;   // lane within group

    const int qbase = blockIdx.x * QTILE + 4 * gi;

    // qq[X] / oo[X]: query (qbase + (c^X)), this lane's 4 owned vecs as 8 ull.
    ull qq[4][8], oo[4][8];
#pragma unroll
    for (int X = 0; X < 4; X++) {
        const ulonglong2* Qrow =
            (const ulonglong2*)(g_Q + ((size_t)bh * Tdim + qbase + (c ^ X)) * HD);
#pragma unroll
        for (int u = 0; u < 4; u++) {
            ulonglong2 v = Qrow[4 * u + c];
            qq[X][2 * u]     = v.x;
            qq[X][2 * u + 1] = v.y;
            oo[X][2 * u]     = 0ULL;
            oo[X][2 * u + 1] = 0ULL;
        }
    }

    float m  = -1e30f;        // online-softmax state for the OWNED query (slot 0)
    float l0 = 0.f, l1 = 0.f;

    const ulonglong2* Kbase = (const ulonglong2*)(g_K + (size_t)bh * Tdim * HD);
    const ulonglong2* Vbase = (const ulonglong2*)(g_V + (size_t)bh * Tdim * HD);

    const int i0 = threadIdx.x;            // tile-load vec indices
    const int i1 = threadIdx.x + THREADS;

    // Prologue: stages 0..2 in flight.
#pragma unroll
    for (int pre = 0; pre < STAGES - 1; pre++) {
        cp_async16(&Ks[pre][i0], &Kbase[pre * TILE_V2 + i0]);
        cp_async16(&Ks[pre][i1], &Kbase[pre * TILE_V2 + i1]);
        cp_async16(&Vs[pre][i0], &Vbase[pre * TILE_V2 + i0]);
        cp_async16(&Vs[pre][i1], &Vbase[pre * TILE_V2 + i1]);
        cp_commit();
    }

    for (int kt = 0; kt < NT; kt++) {
        const int st = kt & (STAGES - 1);

        cp_wait2();          // tile kt complete (<=2 newer groups pending)
        __syncthreads();     // ... and visible to all threads

        // Issue load for tile kt+3 into the stage consumed at kt-1.
        if (kt + STAGES - 1 < NT) {
            const int ns = (kt + STAGES - 1) & (STAGES - 1);
            const ulonglong2* Kn = Kbase + (kt + STAGES - 1) * TILE_V2;
            const ulonglong2* Vn = Vbase + (kt + STAGES - 1) * TILE_V2;
            cp_async16(&Ks[ns][i0], &Kn[i0]);
            cp_async16(&Ks[ns][i1], &Kn[i1]);
            cp_async16(&Vs[ns][i0], &Vn[i0]);
            cp_async16(&Vs[ns][i1], &Vn[i1]);
        }
        cp_commit();  // commit every iteration so wait_group counting stays uniform

        // ---- Scores: quarter-dim partials for 4 queries, 3 shfl/key. ----
        float s[KT];
        float tmax = m;
#pragma unroll
        for (int j = 0; j < KT; j++) {
            const ulonglong2* krow = &Ks[st][j * ROW_V2];
            ulonglong2 kv0 = krow[c];
            ulonglong2 kv1 = krow[4 + c];
            ulonglong2 kv2 = krow[8 + c];
            ulonglong2 kv3 = krow[12 + c];

            float r[4];
#pragma unroll
            for (int X = 0; X < 4; X++) {
                ull a = 0ULL, bch = 0ULL;
                a   = fma2(qq[X][0], kv0.x, a);
                a   = fma2(qq[X][1], kv0.y, a);
                a   = fma2(qq[X][2], kv1.x, a);
                a   = fma2(qq[X][3], kv1.y, a);
                bch = fma2(qq[X][4], kv2.x, bch);
                bch = fma2(qq[X][5], kv2.y, bch);
                bch = fma2(qq[X][6], kv3.x, bch);
                bch = fma2(qq[X][7], kv3.y, bch);
                r[X] = hadd2(a) + hadd2(bch);
            }
            // Transpose-reduce: s_own = sum over 4 lanes of their partial for
            // THIS lane's query.
            const float u  = r[0] + __shfl_xor_sync(0xffffffffu, r[1], 1);
            const float u2 = r[2] + __shfl_xor_sync(0xffffffffu, r[3], 1);
            const float sc = u + __shfl_xor_sync(0xffffffffu, u2, 2);
            s[j] = sc;
            tmax = fmaxf(tmax, sc);
        }

        // ---- Online softmax for the owned query; exp in place of s. ----
        const float corr = __expf(m - tmax);
        m = tmax;
#pragma unroll
        for (int j = 0; j < KT; j++) s[j] = __expf(s[j] - m);

        l0 = l0 * corr;
        l1 = l1 * corr;
#pragma unroll
        for (int j = 0; j < KT; j += 2) { l0 += s[j]; l1 += s[j + 1]; }

        // Rescale all 4 query accumulators with their per-query corr.
        const float corr1 = __shfl_xor_sync(0xffffffffu, corr, 1);
        const float corr2 = __shfl_xor_sync(0xffffffffu, corr, 2);
        const float corr3 = __shfl_xor_sync(0xffffffffu, corr1, 2);
        const ull c0 = pack2(corr,  corr);
        const ull c1 = pack2(corr1, corr1);
        const ull c2 = pack2(corr2, corr2);
        const ull c3 = pack2(corr3, corr3);
#pragma unroll
        for (int i = 0; i < 8; i++) {
            oo[0][i] = mul2(oo[0][i], c0);
            oo[1][i] = mul2(oo[1][i], c1);
            oo[2][i] = mul2(oo[2][i], c2);
            oo[3][i] = mul2(oo[3][i], c3);
        }

        // ---- P.V: one V read serves 4 queries; 3 shfl/key broadcast. ----
#pragma unroll
        for (int j = 0; j < KT; j++) {
            const float p0 = s[j];
            const float p1 = __shfl_xor_sync(0xffffffffu, p0, 1);
            const float p2 = __shfl_xor_sync(0xffffffffu, p0, 2);
            const float p3 = __shfl_xor_sync(0xffffffffu, p1, 2);
            const ull P0 = pack2(p0, p0);
            const ull P1 = pack2(p1, p1);
            const ull P2 = pack2(p2, p2);
            const ull P3 = pack2(p3, p3);

            const ulonglong2* vrow = &Vs[st][j * ROW_V2];
#pragma unroll
            for (int u = 0; u < 4; u++) {
                ulonglong2 vv = vrow[4 * u + c];
                oo[0][2 * u]     = fma2(P0, vv.x, oo[0][2 * u]);
                oo[0][2 * u + 1] = fma2(P0, vv.y, oo[0][2 * u + 1]);
                oo[1][2 * u]     = fma2(P1, vv.x, oo[1][2 * u]);
                oo[1][2 * u + 1] = fma2(P1, vv.y, oo[1][2 * u + 1]);
                oo[2][2 * u]     = fma2(P2, vv.x, oo[2][2 * u]);
                oo[2][2 * u + 1] = fma2(P2, vv.y, oo[2][2 * u + 1]);
                oo[3][2 * u]     = fma2(P3, vv.x, oo[3][2 * u]);
                oo[3][2 * u + 1] = fma2(P3, vv.y, oo[3][2 * u + 1]);
            }
        }
    }

    // ---- Epilogue: exchange l, normalize, write 4 query rows' owned vecs. ----
    const float lo_own = l0 + l1;
    const float lo1 = __shfl_xor_sync(0xffffffffu, lo_own, 1);
    const float lo2 = __shfl_xor_sync(0xffffffffu, lo_own, 2);
    const float lo3 = __shfl_xor_sync(0xffffffffu, lo1, 2);
    const float iv0 = 1.f / lo_own;
    const float iv1 = 1.f / lo1;
    const float iv2 = 1.f / lo2;
    const float iv3 = 1.f / lo3;
    const ull inv[4] = { pack2(iv0, iv0), pack2(iv1, iv1),
                         pack2(iv2, iv2), pack2(iv3, iv3) };

#pragma unroll
    for (int X = 0; X < 4; X++) {
        ulonglong2* orow =
            (ulonglong2*)(out + ((size_t)(b * Tdim + qbase + (c ^ X))) * Edim + h * HD);
#pragma unroll
        for (int u = 0; u < 4; u++) {
            ulonglong2 v;
            v.x = mul2(oo[X][2 * u],     inv[X]);
            v.y = mul2(oo[X][2 * u + 1], inv[X]);
            orow[4 * u + c] = v;
        }
    }
}

// ---------------------------------------------------------------------------
extern "C" void kernel_launch(void* const* d_in, const int* in_sizes, int n_in,
                              void* d_out, int out_size)
{
    const float* x    = (const float*)d_in[0];   // [2, 2048, 1024]
    const float* W    = (const float*)d_in[1];   // [64, 192]
    const float* bias = (const float*)d_in[2];   // [192]
    float* out = (float*)d_out;                  // [2, 2048, 1024]

    qkv_proj_kernel<<<Bdim * Tdim, QKV3>>>(x, W, bias);

    dim3 grid(Tdim / QTILE, Bdim * Hdim);   // 16 x 32 = 512 blocks
    attn_kernel<<<grid, THREADS>>>(out);
}

// round 8
// speedup vs baseline: 1.9905x; 1.9905x over previous
#include <cuda_runtime.h>
#include <cstdint>

#define Bdim 2
#define Tdim 2048
#define Edim 1024
#define Hdim 16
#define HD 64
#define QKV3 192

// Attention tiling
#define NW 4               // warps per block
#define MBLK 64            // queries per block (16 per warp)
#define NTILE 64           // keys per iteration
#define NIT (Tdim / NTILE) // 32
#define KSTR 68            // smem stride (floats) for K tile: conflict-free B frags
#define VSTR 72            // smem stride for V tile
#define PSTR 68            // smem stride for P staging

// Scratch: Q/K/V in [B, H, T, HD] layout, values pre-rounded to tf32.
__device__ float g_Q[Bdim * Hdim * Tdim * HD];
__device__ float g_K[Bdim * Hdim * Tdim * HD];
__device__ float g_V[Bdim * Hdim * Tdim * HD];

typedef unsigned long long ull;

// ---------------------------------------------------------------------------
// helpers
// ---------------------------------------------------------------------------
__device__ __forceinline__ ull fma2(ull a, ull b, ull c) {
    ull d;
    asm("fma.rn.f32x2 %0, %1, %2, %3;" : "=l"(d) : "l"(a), "l"(b), "l"(c));
    return d;
}
__device__ __forceinline__ ull pack2(float lo, float hi) {
    ull r;
    asm("mov.b64 %0, {%1, %2};" : "=l"(r) : "f"(lo), "f"(hi));
    return r;
}
__device__ __forceinline__ float hadd2(ull v) {
    float lo, hi;
    asm("mov.b64 {%0, %1}, %2;" : "=f"(lo), "=f"(hi) : "l"(v));
    return lo + hi;
}
__device__ __forceinline__ uint32_t tf32r(float f) {
    uint32_t u;
    asm("cvt.rna.tf32.f32 %0, %1;" : "=r"(u) : "f"(f));
    return u;
}
__device__ __forceinline__ void mma_tf32(
    float& c0, float& c1, float& c2, float& c3,
    uint32_t a0, uint32_t a1, uint32_t a2, uint32_t a3,
    uint32_t b0, uint32_t b1)
{
    asm volatile(
        "mma.sync.aligned.m16n8k8.row.col.f32.tf32.tf32.f32 "
        "{%0,%1,%2,%3}, {%4,%5,%6,%7}, {%8,%9}, {%0,%1,%2,%3};"
        : "+f"(c0), "+f"(c1), "+f"(c2), "+f"(c3)
        : "r"(a0), "r"(a1), "r"(a2), "r"(a3), "r"(b0), "r"(b1));
}
__device__ __forceinline__ void cp_async16(void* smem_dst, const void* gmem_src) {
    uint32_t s = (uint32_t)__cvta_generic_to_shared(smem_dst);
    asm volatile("cp.async.cg.shared.global [%0], [%1], 16;"
                 :: "r"(s), "l"(gmem_src) : "memory");
}
__device__ __forceinline__ void cp_commit() {
    asm volatile("cp.async.commit_group;" ::: "memory");
}
__device__ __forceinline__ void cp_wait1() {
    asm volatile("cp.async.wait_group 1;" ::: "memory");
}

// ---------------------------------------------------------------------------
// Kernel 1: QKV projection (f32x2 inner loop, verified). Output rounded to
// tf32 so the attention MMAs can consume the bits directly.
// ---------------------------------------------------------------------------
__global__ __launch_bounds__(QKV3) void qkv_proj_kernel(
    const float* __restrict__ x,      // [B, T, E]
    const float* __restrict__ W,      // [HD, 3*HD]
    const float* __restrict__ bias)   // [3*HD]
{
    __shared__ __align__(16) float xs[Edim];
    const int bt = blockIdx.x;
    const int b  = bt / Tdim;
    const int t  = bt % Tdim;

    const float* xrow = x + (size_t)bt * Edim;
    for (int i = threadIdx.x; i < Edim; i += QKV3) xs[i] = xrow[i];
    __syncthreads();

    const int d = threadIdx.x;  // 0..191

    ull w2[HD / 2];
#pragma unroll 8
    for (int k2 = 0; k2 < HD / 2; k2++)
        w2[k2] = pack2(W[(2 * k2) * QKV3 + d], W[(2 * k2 + 1) * QKV3 + d]);

    const float bv = bias[d];
    const ull* xs2 = (const ull*)xs;

    float acc[Hdim];
#pragma unroll
    for (int h = 0; h < Hdim; h++) {
        ull a0 = 0ULL, a1 = 0ULL;
#pragma unroll
        for (int k2 = 0; k2 < HD / 2; k2 += 2) {
            a0 = fma2(xs2[h * (HD / 2) + k2],     w2[k2],     a0);
            a1 = fma2(xs2[h * (HD / 2) + k2 + 1], w2[k2 + 1], a1);
        }
        acc[h] = bv + (hadd2(a0) + hadd2(a1));
    }

#pragma unroll
    for (int h = 0; h < Hdim; h++) {
        const size_t off = ((size_t)(b * Hdim + h) * Tdim + t) * HD;
        if (d < HD) {
            // 1/sqrt(64) folded into Q, then tf32 rounding
            g_Q[off + d] = __uint_as_float(tf32r(acc[h] * 0.125f));
        } else if (d < 2 * HD) {
            g_K[off + d - HD] = __uint_as_float(tf32r(acc[h]));
        } else {
            g_V[off + d - 2 * HD] = __uint_as_float(tf32r(acc[h]));
        }
    }
}

// ---------------------------------------------------------------------------
// Kernel 2: tf32 tensor-core flash attention.
// Block: 4 warps, 64 query rows (16 per warp). Iterate 64-key tiles.
// S = Q K^T via m16n8k8 (Q frags in regs, K B-frags from smem).
// Online softmax on C fragments; P staged in smem; O += P V via m16n8k8.
// ---------------------------------------------------------------------------
#define SMK_FLOATS (2 * NTILE * KSTR)          // 8704
#define SMV_FLOATS (2 * NTILE * VSTR)          // 9216
#define SMP_FLOATS (NW * 16 * PSTR)            // 4352
#define SMEM_FLOATS (SMK_FLOATS + SMV_FLOATS + SMP_FLOATS)
#define SMEM_BYTES (SMEM_FLOATS * 4)           // 89088

__global__ void attn_kernel(float* __restrict__ out)
{
    extern __shared__ __align__(16) float sm[];
    float* smK = sm;                           // [2][NTILE][KSTR]
    float* smV = sm + SMK_FLOATS;              // [2][NTILE][VSTR]
    float* smP = sm + SMK_FLOATS + SMV_FLOATS; // [NW][16][PSTR]

    const int tid  = threadIdx.x;
    const int w    = tid >> 5;
    const int lane = tid & 31;
    const int gid  = lane >> 2;   // 0..7  (row-group within fragment)
    const int tig  = lane & 3;    // 0..3

    const int bh = blockIdx.y;
    const int b  = bh >> 4;
    const int h  = bh & 15;

    const float* Kg = g_K + (size_t)bh * Tdim * HD;
    const float* Vg = g_V + (size_t)bh * Tdim * HD;

    // ---- issue tile 0 loads ----
    {
#pragma unroll
        for (int i = 0; i < 8; i++) {
            int v = tid + 128 * i;           // 0..1023
            int row = v >> 4, c4 = (v & 15) * 4;
            cp_async16(&smK[row * KSTR + c4], Kg + row * HD + c4);
            cp_async16(&smV[row * VSTR + c4], Vg + row * HD + c4);
        }
        cp_commit();
    }

    // ---- Q fragments (this warp's 16 rows), already tf32 bits ----
    const int qrow0 = blockIdx.x * MBLK + w * 16 + gid;
    const float* Qp = g_Q + ((size_t)bh * Tdim + qrow0) * HD;
    uint32_t qf[8][4];
#pragma unroll
    for (int kt = 0; kt < 8; kt++) {
        qf[kt][0] = __float_as_uint(Qp[kt * 8 + tig]);
        qf[kt][1] = __float_as_uint(Qp[8 * HD + kt * 8 + tig]);
        qf[kt][2] = __float_as_uint(Qp[kt * 8 + tig + 4]);
        qf[kt][3] = __float_as_uint(Qp[8 * HD + kt * 8 + tig + 4]);
    }

    float o[8][4];
#pragma unroll
    for (int nt = 0; nt < 8; nt++)
#pragma unroll
        for (int i = 0; i < 4; i++) o[nt][i] = 0.f;

    float m0 = -1e30f, m1 = -1e30f;
    float l0 = 0.f,    l1 = 0.f;

    float* Pw = smP + w * 16 * PSTR;

    for (int kt_it = 0; kt_it < NIT; kt_it++) {
        const int st = kt_it & 1;

        // issue next tile into the other buffer (freed by last iter's barrier)
        if (kt_it + 1 < NIT) {
            const int ns = (kt_it + 1) & 1;
            const float* Kn = Kg + (size_t)(kt_it + 1) * NTILE * HD;
            const float* Vn = Vg + (size_t)(kt_it + 1) * NTILE * HD;
#pragma unroll
            for (int i = 0; i < 8; i++) {
                int v = tid + 128 * i;
                int row = v >> 4, c4 = (v & 15) * 4;
                cp_async16(&smK[ns * NTILE * KSTR + row * KSTR + c4],
                           Kn + row * HD + c4);
                cp_async16(&smV[ns * NTILE * VSTR + row * VSTR + c4],
                           Vn + row * HD + c4);
            }
        }
        cp_commit();
        cp_wait1();          // tile kt_it fully landed
        __syncthreads();     // visible to all threads

        const float* Kt = smK + st * NTILE * KSTR;
        const float* Vt = smV + st * NTILE * VSTR;

        // ---- S = Q K^T : 8 n-tiles x 8 k-tiles of m16n8k8 ----
        float sc[8][4];
#pragma unroll
        for (int nt = 0; nt < 8; nt++) {
            float c0 = 0.f, c1 = 0.f, c2 = 0.f, c3 = 0.f;
#pragma unroll
            for (int kt = 0; kt < 8; kt++) {
                const float* kb = Kt + (nt * 8 + gid) * KSTR + kt * 8 + tig;
                uint32_t b0 = __float_as_uint(kb[0]);
                uint32_t b1 = __float_as_uint(kb[4]);
                mma_tf32(c0, c1, c2, c3,
                         qf[kt][0], qf[kt][1], qf[kt][2], qf[kt][3], b0, b1);
            }
            sc[nt][0] = c0; sc[nt][1] = c1; sc[nt][2] = c2; sc[nt][3] = c3;
        }

        // ---- online softmax (rows r0=gid, r1=gid+8 of this warp tile) ----
        float rm0 = -1e30f, rm1 = -1e30f;
#pragma unroll
        for (int nt = 0; nt < 8; nt++) {
            rm0 = fmaxf(rm0, fmaxf(sc[nt][0], sc[nt][1]));
            rm1 = fmaxf(rm1, fmaxf(sc[nt][2], sc[nt][3]));
        }
        rm0 = fmaxf(rm0, __shfl_xor_sync(0xffffffffu, rm0, 1));
        rm0 = fmaxf(rm0, __shfl_xor_sync(0xffffffffu, rm0, 2));
        rm1 = fmaxf(rm1, __shfl_xor_sync(0xffffffffu, rm1, 1));
        rm1 = fmaxf(rm1, __shfl_xor_sync(0xffffffffu, rm1, 2));

        const float nm0 = fmaxf(m0, rm0);
        const float nm1 = fmaxf(m1, rm1);
        const float corr0 = __expf(m0 - nm0);
        const float corr1 = __expf(m1 - nm1);
        m0 = nm0; m1 = nm1;

        float ls0 = 0.f, ls1 = 0.f;
#pragma unroll
        for (int nt = 0; nt < 8; nt++) {
            // exp, round to tf32, sum the ROUNDED values into l
            float p0 = __uint_as_float(tf32r(__expf(sc[nt][0] - m0)));
            float p1 = __uint_as_float(tf32r(__expf(sc[nt][1] - m0)));
            float p2 = __uint_as_float(tf32r(__expf(sc[nt][2] - m1)));
            float p3 = __uint_as_float(tf32r(__expf(sc[nt][3] - m1)));
            ls0 += p0 + p1;
            ls1 += p2 + p3;
            // stage P (tf32 bits) for the PV MMA
            float2* d0 = (float2*)&Pw[gid * PSTR + nt * 8 + 2 * tig];
            float2* d1 = (float2*)&Pw[(gid + 8) * PSTR + nt * 8 + 2 * tig];
            *d0 = make_float2(p0, p1);
            *d1 = make_float2(p2, p3);
        }
        l0 = l0 * corr0 + ls0;
        l1 = l1 * corr1 + ls1;

#pragma unroll
        for (int nt = 0; nt < 8; nt++) {
            o[nt][0] *= corr0; o[nt][1] *= corr0;
            o[nt][2] *= corr1; o[nt][3] *= corr1;
        }
        __syncwarp();

        // ---- P fragments (A operand of PV), one set per key-ktile ----
        uint32_t pa[8][4];
#pragma unroll
        for (int kt = 0; kt < 8; kt++) {
            pa[kt][0] = __float_as_uint(Pw[gid * PSTR + kt * 8 + tig]);
            pa[kt][1] = __float_as_uint(Pw[(gid + 8) * PSTR + kt * 8 + tig]);
            pa[kt][2] = __float_as_uint(Pw[gid * PSTR + kt * 8 + tig + 4]);
            pa[kt][3] = __float_as_uint(Pw[(gid + 8) * PSTR + kt * 8 + tig + 4]);
        }

        // ---- O += P V ----
#pragma unroll
        for (int nt = 0; nt < 8; nt++) {
#pragma unroll
            for (int kt = 0; kt < 8; kt++) {
                uint32_t b0 = __float_as_uint(
                    Vt[(kt * 8 + tig) * VSTR + nt * 8 + gid]);
                uint32_t b1 = __float_as_uint(
                    Vt[(kt * 8 + tig + 4) * VSTR + nt * 8 + gid]);
                mma_tf32(o[nt][0], o[nt][1], o[nt][2], o[nt][3],
                         pa[kt][0], pa[kt][1], pa[kt][2], pa[kt][3], b0, b1);
            }
        }

        __syncthreads();   // protect smem buffers before next overwrite
    }

    // ---- epilogue: reduce l over the quad, normalize, store ----
    l0 += __shfl_xor_sync(0xffffffffu, l0, 1);
    l0 += __shfl_xor_sync(0xffffffffu, l0, 2);
    l1 += __shfl_xor_sync(0xffffffffu, l1, 1);
    l1 += __shfl_xor_sync(0xffffffffu, l1, 2);
    const float inv0 = 1.f / l0;
    const float inv1 = 1.f / l1;

    float* orow0 = out + ((size_t)(b * Tdim + qrow0)) * Edim + h * HD;
    float* orow1 = orow0 + 8 * (size_t)Edim;
#pragma unroll
    for (int nt = 0; nt < 8; nt++) {
        float2* d0 = (float2*)&orow0[nt * 8 + 2 * tig];
        float2* d1 = (float2*)&orow1[nt * 8 + 2 * tig];
        *d0 = make_float2(o[nt][0] * inv0, o[nt][1] * inv0);
        *d1 = make_float2(o[nt][2] * inv1, o[nt][3] * inv1);
    }
}

// ---------------------------------------------------------------------------
extern "C" void kernel_launch(void* const* d_in, const int* in_sizes, int n_in,
                              void* d_out, int out_size)
{
    const float* x    = (const float*)d_in[0];   // [2, 2048, 1024]
    const float* W    = (const float*)d_in[1];   // [64, 192]
    const float* bias = (const float*)d_in[2];   // [192]
    float* out = (float*)d_out;                  // [2, 2048, 1024]

    qkv_proj_kernel<<<Bdim * Tdim, QKV3>>>(x, W, bias);

    cudaFuncSetAttribute(attn_kernel,
                         cudaFuncAttributeMaxDynamicSharedMemorySize,
                         SMEM_BYTES);
    dim3 grid(Tdim / MBLK, Bdim * Hdim);   // 32 x 32 = 1024 blocks
    attn_kernel<<<grid, 32 * NW, SMEM_BYTES>>>(out);
}

// round 9
// speedup vs baseline: 2.8545x; 1.4340x over previous
#include <cuda_runtime.h>
#include <cstdint>

#define Bdim 2
#define Tdim 2048
#define Edim 1024
#define Hdim 16
#define HD 64
#define QKV3 192
#define TPB 4              // (b,t) rows per QKV block

// Attention tiling
#define NW 4               // warps per block
#define MBLK 128           // queries per block (32 per warp: two m16 tiles)
#define NTILE 32           // keys per iteration
#define NIT (Tdim / NTILE) // 64
#define KSTR 68            // K tile stride (floats): QK B-frags conflict-free
#define VSTR 72            // V tile stride: PV B-frags conflict-free
#define PSTR 36            // P staging stride

#define LOG2E 1.4426950408889634f

// Scratch: Q/K/V in [B, H, T, HD] layout, tf32-rounded.
// Q additionally pre-scaled by 0.125*log2(e) (softmax in exp2 domain).
__device__ float g_Q[Bdim * Hdim * Tdim * HD];
__device__ float g_K[Bdim * Hdim * Tdim * HD];
__device__ float g_V[Bdim * Hdim * Tdim * HD];

typedef unsigned long long ull;

// ---------------------------------------------------------------------------
// helpers
// ---------------------------------------------------------------------------
__device__ __forceinline__ ull fma2(ull a, ull b, ull c) {
    ull d;
    asm("fma.rn.f32x2 %0, %1, %2, %3;" : "=l"(d) : "l"(a), "l"(b), "l"(c));
    return d;
}
__device__ __forceinline__ ull pack2(float lo, float hi) {
    ull r;
    asm("mov.b64 %0, {%1, %2};" : "=l"(r) : "f"(lo), "f"(hi));
    return r;
}
__device__ __forceinline__ float hadd2(ull v) {
    float lo, hi;
    asm("mov.b64 {%0, %1}, %2;" : "=f"(lo), "=f"(hi) : "l"(v));
    return lo + hi;
}
__device__ __forceinline__ uint32_t tf32r(float f) {
    uint32_t u;
    asm("cvt.rna.tf32.f32 %0, %1;" : "=r"(u) : "f"(f));
    return u;
}
__device__ __forceinline__ float ex2(float x) {
    float y;
    asm("ex2.approx.ftz.f32 %0, %1;" : "=f"(y) : "f"(x));
    return y;
}
__device__ __forceinline__ void mma_tf32(
    float& c0, float& c1, float& c2, float& c3,
    uint32_t a0, uint32_t a1, uint32_t a2, uint32_t a3,
    uint32_t b0, uint32_t b1)
{
    asm volatile(
        "mma.sync.aligned.m16n8k8.row.col.f32.tf32.tf32.f32 "
        "{%0,%1,%2,%3}, {%4,%5,%6,%7}, {%8,%9}, {%0,%1,%2,%3};"
        : "+f"(c0), "+f"(c1), "+f"(c2), "+f"(c3)
        : "r"(a0), "r"(a1), "r"(a2), "r"(a3), "r"(b0), "r"(b1));
}
__device__ __forceinline__ void cp_async16(void* smem_dst, const void* gmem_src) {
    uint32_t s = (uint32_t)__cvta_generic_to_shared(smem_dst);
    asm volatile("cp.async.cg.shared.global [%0], [%1], 16;"
                 :: "r"(s), "l"(gmem_src) : "memory");
}
__device__ __forceinline__ void cp_commit() {
    asm volatile("cp.async.commit_group;" ::: "memory");
}
__device__ __forceinline__ void cp_wait1() {
    asm volatile("cp.async.wait_group 1;" ::: "memory");
}

// ---------------------------------------------------------------------------
// Kernel 1: QKV projection, 4 (b,t) rows per block to amortize W registers.
// ---------------------------------------------------------------------------
__global__ __launch_bounds__(QKV3) void qkv_proj_kernel(
    const float* __restrict__ x,      // [B, T, E]
    const float* __restrict__ W,      // [HD, 3*HD]
    const float* __restrict__ bias)   // [3*HD]
{
    __shared__ __align__(16) float xs[TPB * Edim];
    const int bt0 = blockIdx.x * TPB;

    const float* xsrc = x + (size_t)bt0 * Edim;
    for (int i = threadIdx.x; i < TPB * Edim; i += QKV3) xs[i] = xsrc[i];
    __syncthreads();

    const int d = threadIdx.x;  // 0..191

    ull w2[HD / 2];
#pragma unroll 8
    for (int k2 = 0; k2 < HD / 2; k2++)
        w2[k2] = pack2(W[(2 * k2) * QKV3 + d], W[(2 * k2 + 1) * QKV3 + d]);

    const float bv = bias[d];

#pragma unroll
    for (int r = 0; r < TPB; r++) {
        const int bt = bt0 + r;
        const int b  = bt / Tdim;
        const int t  = bt % Tdim;
        const ull* xs2 = (const ull*)(xs + r * Edim);

        float acc[Hdim];
#pragma unroll
        for (int h = 0; h < Hdim; h++) {
            ull a0 = 0ULL, a1 = 0ULL;
#pragma unroll
            for (int k2 = 0; k2 < HD / 2; k2 += 2) {
                a0 = fma2(xs2[h * (HD / 2) + k2],     w2[k2],     a0);
                a1 = fma2(xs2[h * (HD / 2) + k2 + 1], w2[k2 + 1], a1);
            }
            acc[h] = bv + (hadd2(a0) + hadd2(a1));
        }

#pragma unroll
        for (int h = 0; h < Hdim; h++) {
            const size_t off = ((size_t)(b * Hdim + h) * Tdim + t) * HD;
            if (d < HD) {
                // fold softmax scale AND log2(e) into Q, round to tf32
                g_Q[off + d] =
                    __uint_as_float(tf32r(acc[h] * (0.125f * LOG2E)));
            } else if (d < 2 * HD) {
                g_K[off + d - HD] = __uint_as_float(tf32r(acc[h]));
            } else {
                g_V[off + d - 2 * HD] = __uint_as_float(tf32r(acc[h]));
            }
        }
    }
}

// ---------------------------------------------------------------------------
// Kernel 2: tf32 tensor-core flash attention, m32 per warp.
// Each warp owns 32 query rows (two m16 tiles mt=0,1) that SHARE every
// B-fragment load. 32-key tiles, cp.async double buffered.
// ---------------------------------------------------------------------------
#define SMK_FLOATS (2 * NTILE * KSTR)   // 4352
#define SMV_FLOATS (2 * NTILE * VSTR)   // 4608
#define SMP_FLOATS (NW * 32 * PSTR)     // 4608
#define SMEM_BYTES ((SMK_FLOATS + SMV_FLOATS + SMP_FLOATS) * 4)  // 54272

__global__ __launch_bounds__(32 * NW) void attn_kernel(float* __restrict__ out)
{
    extern __shared__ __align__(16) float sm[];
    float* smK = sm;                           // [2][NTILE][KSTR]
    float* smV = sm + SMK_FLOATS;              // [2][NTILE][VSTR]
    float* smP = sm + SMK_FLOATS + SMV_FLOATS; // [NW][32][PSTR]

    const int tid  = threadIdx.x;
    const int w    = tid >> 5;
    const int lane = tid & 31;
    const int gid  = lane >> 2;   // 0..7
    const int tig  = lane & 3;    // 0..3

    const int bh = blockIdx.y;
    const int b  = bh >> 4;
    const int h  = bh & 15;

    const float* Kg = g_K + (size_t)bh * Tdim * HD;
    const float* Vg = g_V + (size_t)bh * Tdim * HD;

    // ---- issue tile 0 (32 rows x 64 floats per array = 4 cp/thread each) ----
#pragma unroll
    for (int i = 0; i < 4; i++) {
        int v = tid + 128 * i;            // 0..511
        int row = v >> 4, c4 = (v & 15) * 4;
        cp_async16(&smK[row * KSTR + c4], Kg + row * HD + c4);
        cp_async16(&smV[row * VSTR + c4], Vg + row * HD + c4);
    }
    cp_commit();

    // ---- Q fragments: two m16 tiles ----
    const int qrow0 = blockIdx.x * MBLK + w * 32 + gid;
    const float* Qp = g_Q + ((size_t)bh * Tdim + qrow0) * HD;
    uint32_t qf[2][8][4];
#pragma unroll
    for (int mt = 0; mt < 2; mt++) {
        const float* Qm = Qp + (size_t)(mt * 16) * HD;
#pragma unroll
        for (int kt = 0; kt < 8; kt++) {
            qf[mt][kt][0] = __float_as_uint(Qm[kt * 8 + tig]);
            qf[mt][kt][1] = __float_as_uint(Qm[8 * HD + kt * 8 + tig]);
            qf[mt][kt][2] = __float_as_uint(Qm[kt * 8 + tig + 4]);
            qf[mt][kt][3] = __float_as_uint(Qm[8 * HD + kt * 8 + tig + 4]);
        }
    }

    float o[2][8][4];
#pragma unroll
    for (int mt = 0; mt < 2; mt++)
#pragma unroll
        for (int nt = 0; nt < 8; nt++)
#pragma unroll
            for (int i = 0; i < 4; i++) o[mt][nt][i] = 0.f;

    float mrow[2][2], lrow[2][2];
#pragma unroll
    for (int mt = 0; mt < 2; mt++) {
        mrow[mt][0] = -1e30f; mrow[mt][1] = -1e30f;
        lrow[mt][0] = 0.f;    lrow[mt][1] = 0.f;
    }

    float* Pw = smP + w * 32 * PSTR;

    for (int it = 0; it < NIT; it++) {
        const int st = it & 1;

        if (it + 1 < NIT) {
            const int ns = (it + 1) & 1;
            const float* Kn = Kg + (size_t)(it + 1) * NTILE * HD;
            const float* Vn = Vg + (size_t)(it + 1) * NTILE * HD;
#pragma unroll
            for (int i = 0; i < 4; i++) {
                int v = tid + 128 * i;
                int row = v >> 4, c4 = (v & 15) * 4;
                cp_async16(&smK[ns * NTILE * KSTR + row * KSTR + c4],
                           Kn + row * HD + c4);
                cp_async16(&smV[ns * NTILE * VSTR + row * VSTR + c4],
                           Vn + row * HD + c4);
            }
        }
        cp_commit();
        cp_wait1();
        __syncthreads();

        const float* Kt = smK + st * NTILE * KSTR;
        const float* Vt = smV + st * NTILE * VSTR;

        // ---- S = Q K^T : 4 key n-tiles, B-frags shared by both m-tiles ----
        float sc[2][4][4];
#pragma unroll
        for (int nt = 0; nt < 4; nt++) {
#pragma unroll
            for (int mt = 0; mt < 2; mt++)
#pragma unroll
                for (int i = 0; i < 4; i++) sc[mt][nt][i] = 0.f;
#pragma unroll
            for (int kt = 0; kt < 8; kt++) {
                const float* kb = Kt + (nt * 8 + gid) * KSTR + kt * 8 + tig;
                uint32_t b0 = __float_as_uint(kb[0]);
                uint32_t b1 = __float_as_uint(kb[4]);
                mma_tf32(sc[0][nt][0], sc[0][nt][1], sc[0][nt][2], sc[0][nt][3],
                         qf[0][kt][0], qf[0][kt][1], qf[0][kt][2], qf[0][kt][3],
                         b0, b1);
                mma_tf32(sc[1][nt][0], sc[1][nt][1], sc[1][nt][2], sc[1][nt][3],
                         qf[1][kt][0], qf[1][kt][1], qf[1][kt][2], qf[1][kt][3],
                         b0, b1);
            }
        }

        // ---- online softmax (exp2 domain) + P staging ----
#pragma unroll
        for (int mt = 0; mt < 2; mt++) {
            float rm0 = -1e30f, rm1 = -1e30f;
#pragma unroll
            for (int nt = 0; nt < 4; nt++) {
                rm0 = fmaxf(rm0, fmaxf(sc[mt][nt][0], sc[mt][nt][1]));
                rm1 = fmaxf(rm1, fmaxf(sc[mt][nt][2], sc[mt][nt][3]));
            }
            rm0 = fmaxf(rm0, __shfl_xor_sync(0xffffffffu, rm0, 1));
            rm0 = fmaxf(rm0, __shfl_xor_sync(0xffffffffu, rm0, 2));
            rm1 = fmaxf(rm1, __shfl_xor_sync(0xffffffffu, rm1, 1));
            rm1 = fmaxf(rm1, __shfl_xor_sync(0xffffffffu, rm1, 2));

            const float nm0 = fmaxf(mrow[mt][0], rm0);
            const float nm1 = fmaxf(mrow[mt][1], rm1);
            const float corr0 = ex2(mrow[mt][0] - nm0);
            const float corr1 = ex2(mrow[mt][1] - nm1);
            mrow[mt][0] = nm0; mrow[mt][1] = nm1;

            float ls0 = 0.f, ls1 = 0.f;
#pragma unroll
            for (int nt = 0; nt < 4; nt++) {
                float p0 = __uint_as_float(tf32r(ex2(sc[mt][nt][0] - nm0)));
                float p1 = __uint_as_float(tf32r(ex2(sc[mt][nt][1] - nm0)));
                float p2 = __uint_as_float(tf32r(ex2(sc[mt][nt][2] - nm1)));
                float p3 = __uint_as_float(tf32r(ex2(sc[mt][nt][3] - nm1)));
                ls0 += p0 + p1;
                ls1 += p2 + p3;
                float2* d0 = (float2*)&Pw[(mt * 16 + gid) * PSTR + nt * 8 + 2 * tig];
                float2* d1 = (float2*)&Pw[(mt * 16 + gid + 8) * PSTR + nt * 8 + 2 * tig];
                *d0 = make_float2(p0, p1);
                *d1 = make_float2(p2, p3);
            }
            lrow[mt][0] = lrow[mt][0] * corr0 + ls0;
            lrow[mt][1] = lrow[mt][1] * corr1 + ls1;

#pragma unroll
            for (int nt = 0; nt < 8; nt++) {
                o[mt][nt][0] *= corr0; o[mt][nt][1] *= corr0;
                o[mt][nt][2] *= corr1; o[mt][nt][3] *= corr1;
            }
        }
        __syncwarp();

        // ---- P fragments (A of PV) ----
        uint32_t pa[2][4][4];
#pragma unroll
        for (int mt = 0; mt < 2; mt++)
#pragma unroll
            for (int kt = 0; kt < 4; kt++) {
                const float* pr0 = &Pw[(mt * 16 + gid) * PSTR + kt * 8];
                const float* pr1 = &Pw[(mt * 16 + gid + 8) * PSTR + kt * 8];
                pa[mt][kt][0] = __float_as_uint(pr0[tig]);
                pa[mt][kt][1] = __float_as_uint(pr1[tig]);
                pa[mt][kt][2] = __float_as_uint(pr0[tig + 4]);
                pa[mt][kt][3] = __float_as_uint(pr1[tig + 4]);
            }

        // ---- O += P V : B-frags shared by both m-tiles ----
#pragma unroll
        for (int nt = 0; nt < 8; nt++) {
#pragma unroll
            for (int kt = 0; kt < 4; kt++) {
                uint32_t b0 = __float_as_uint(
                    Vt[(kt * 8 + tig) * VSTR + nt * 8 + gid]);
                uint32_t b1 = __float_as_uint(
                    Vt[(kt * 8 + tig + 4) * VSTR + nt * 8 + gid]);
                mma_tf32(o[0][nt][0], o[0][nt][1], o[0][nt][2], o[0][nt][3],
                         pa[0][kt][0], pa[0][kt][1], pa[0][kt][2], pa[0][kt][3],
                         b0, b1);
                mma_tf32(o[1][nt][0], o[1][nt][1], o[1][nt][2], o[1][nt][3],
                         pa[1][kt][0], pa[1][kt][1], pa[1][kt][2], pa[1][kt][3],
                         b0, b1);
            }
        }

        __syncthreads();
    }

    // ---- epilogue ----
#pragma unroll
    for (int mt = 0; mt < 2; mt++) {
        float l0 = lrow[mt][0], l1 = lrow[mt][1];
        l0 += __shfl_xor_sync(0xffffffffu, l0, 1);
        l0 += __shfl_xor_sync(0xffffffffu, l0, 2);
        l1 += __shfl_xor_sync(0xffffffffu, l1, 1);
        l1 += __shfl_xor_sync(0xffffffffu, l1, 2);
        const float inv0 = 1.f / l0;
        const float inv1 = 1.f / l1;

        float* orow0 = out + ((size_t)(b * Tdim + qrow0 + mt * 16)) * Edim + h * HD;
        float* orow1 = orow0 + 8 * (size_t)Edim;
#pragma unroll
        for (int nt = 0; nt < 8; nt++) {
            float2* d0 = (float2*)&orow0[nt * 8 + 2 * tig];
            float2* d1 = (float2*)&orow1[nt * 8 + 2 * tig];
            *d0 = make_float2(o[mt][nt][0] * inv0, o[mt][nt][1] * inv0);
            *d1 = make_float2(o[mt][nt][2] * inv1, o[mt][nt][3] * inv1);
        }
    }
}

// ---------------------------------------------------------------------------
extern "C" void kernel_launch(void* const* d_in, const int* in_sizes, int n_in,
                              void* d_out, int out_size)
{
    const float* x    = (const float*)d_in[0];   // [2, 2048, 1024]
    const float* W    = (const float*)d_in[1];   // [64, 192]
    const float* bias = (const float*)d_in[2];   // [192]
    float* out = (float*)d_out;                  // [2, 2048, 1024]

    qkv_proj_kernel<<<Bdim * Tdim / TPB, QKV3>>>(x, W, bias);

    cudaFuncSetAttribute(attn_kernel,
                         cudaFuncAttributeMaxDynamicSharedMemorySize,
                         SMEM_BYTES);
    dim3 grid(Tdim / MBLK, Bdim * Hdim);   // 16 x 32 = 512 blocks
    attn_kernel<<<grid, 32 * NW, SMEM_BYTES>>>(out);
}

// round 10
// speedup vs baseline: 3.0239x; 1.0594x over previous
#include <cuda_runtime.h>
#include <cuda_bf16.h>
#include <cstdint>

#define Bdim 2
#define Tdim 2048
#define Edim 1024
#define Hdim 16
#define HD 64
#define QKV3 192
#define TPB 4              // (b,t) rows per QKV block

// Attention tiling
#define NW 4               // warps per block
#define MBLK 128           // queries per block (32 per warp: two m16 tiles)
#define NTILE 32           // keys per iteration
#define NIT (Tdim / NTILE) // 64
#define HSTR 72            // smem row stride in bf16 elems (144 B)
#define HSTRU 36           // ... in u32 units

#define LOG2E 1.4426950408889634f

// Scratch: Q/K/V in [B, H, T, HD] layout, bf16.
// Q pre-scaled by 0.125*log2(e) (softmax in exp2 domain).
__device__ __nv_bfloat16 g_Q[Bdim * Hdim * Tdim * HD];
__device__ __nv_bfloat16 g_K[Bdim * Hdim * Tdim * HD];
__device__ __nv_bfloat16 g_V[Bdim * Hdim * Tdim * HD];

typedef unsigned long long ull;

// ---------------------------------------------------------------------------
// helpers
// ---------------------------------------------------------------------------
__device__ __forceinline__ ull fma2(ull a, ull b, ull c) {
    ull d;
    asm("fma.rn.f32x2 %0, %1, %2, %3;" : "=l"(d) : "l"(a), "l"(b), "l"(c));
    return d;
}
__device__ __forceinline__ ull pack2(float lo, float hi) {
    ull r;
    asm("mov.b64 %0, {%1, %2};" : "=l"(r) : "f"(lo), "f"(hi));
    return r;
}
__device__ __forceinline__ float hadd2(ull v) {
    float lo, hi;
    asm("mov.b64 {%0, %1}, %2;" : "=f"(lo), "=f"(hi) : "l"(v));
    return lo + hi;
}
__device__ __forceinline__ float ex2(float x) {
    float y;
    asm("ex2.approx.ftz.f32 %0, %1;" : "=f"(y) : "f"(x));
    return y;
}
// d = {lo, hi} packed bf16x2
__device__ __forceinline__ uint32_t bf16x2(float hi, float lo) {
    uint32_t d;
    asm("cvt.rn.bf16x2.f32 %0, %1, %2;" : "=r"(d) : "f"(hi), "f"(lo));
    return d;
}
__device__ __forceinline__ void mma_bf16(
    float& c0, float& c1, float& c2, float& c3,
    uint32_t a0, uint32_t a1, uint32_t a2, uint32_t a3,
    uint32_t b0, uint32_t b1)
{
    asm volatile(
        "mma.sync.aligned.m16n8k16.row.col.f32.bf16.bf16.f32 "
        "{%0,%1,%2,%3}, {%4,%5,%6,%7}, {%8,%9}, {%0,%1,%2,%3};"
        : "+f"(c0), "+f"(c1), "+f"(c2), "+f"(c3)
        : "r"(a0), "r"(a1), "r"(a2), "r"(a3), "r"(b0), "r"(b1));
}
__device__ __forceinline__ void ldsm_x4_trans(
    uint32_t& r0, uint32_t& r1, uint32_t& r2, uint32_t& r3, uint32_t saddr)
{
    asm volatile(
        "ldmatrix.sync.aligned.m8n8.x4.trans.shared.b16 {%0,%1,%2,%3}, [%4];"
        : "=r"(r0), "=r"(r1), "=r"(r2), "=r"(r3) : "r"(saddr));
}
__device__ __forceinline__ void cp_async16(uint32_t smem_dst, const void* gmem_src) {
    asm volatile("cp.async.cg.shared.global [%0], [%1], 16;"
                 :: "r"(smem_dst), "l"(gmem_src) : "memory");
}
__device__ __forceinline__ void cp_commit() {
    asm volatile("cp.async.commit_group;" ::: "memory");
}
__device__ __forceinline__ void cp_wait1() {
    asm volatile("cp.async.wait_group 1;" ::: "memory");
}

// ---------------------------------------------------------------------------
// Kernel 1: QKV projection, fp32 math (f32x2), bf16 outputs.
// ---------------------------------------------------------------------------
__global__ __launch_bounds__(QKV3) void qkv_proj_kernel(
    const float* __restrict__ x,      // [B, T, E]
    const float* __restrict__ W,      // [HD, 3*HD]
    const float* __restrict__ bias)   // [3*HD]
{
    __shared__ __align__(16) float xs[TPB * Edim];
    const int bt0 = blockIdx.x * TPB;

    const float* xsrc = x + (size_t)bt0 * Edim;
    for (int i = threadIdx.x; i < TPB * Edim; i += QKV3) xs[i] = xsrc[i];
    __syncthreads();

    const int d = threadIdx.x;  // 0..191

    ull w2[HD / 2];
#pragma unroll 8
    for (int k2 = 0; k2 < HD / 2; k2++)
        w2[k2] = pack2(W[(2 * k2) * QKV3 + d], W[(2 * k2 + 1) * QKV3 + d]);

    const float bv = bias[d];

#pragma unroll
    for (int r = 0; r < TPB; r++) {
        const int bt = bt0 + r;
        const int b  = bt / Tdim;
        const int t  = bt % Tdim;
        const ull* xs2 = (const ull*)(xs + r * Edim);

        float acc[Hdim];
#pragma unroll
        for (int h = 0; h < Hdim; h++) {
            ull a0 = 0ULL, a1 = 0ULL;
#pragma unroll
            for (int k2 = 0; k2 < HD / 2; k2 += 2) {
                a0 = fma2(xs2[h * (HD / 2) + k2],     w2[k2],     a0);
                a1 = fma2(xs2[h * (HD / 2) + k2 + 1], w2[k2 + 1], a1);
            }
            acc[h] = bv + (hadd2(a0) + hadd2(a1));
        }

#pragma unroll
        for (int h = 0; h < Hdim; h++) {
            const size_t off = ((size_t)(b * Hdim + h) * Tdim + t) * HD;
            if (d < HD) {
                g_Q[off + d] = __float2bfloat16(acc[h] * (0.125f * LOG2E));
            } else if (d < 2 * HD) {
                g_K[off + d - HD] = __float2bfloat16(acc[h]);
            } else {
                g_V[off + d - 2 * HD] = __float2bfloat16(acc[h]);
            }
        }
    }
}

// ---------------------------------------------------------------------------
// Kernel 2: bf16 tensor-core flash attention, m32 per warp, register P.
// S C-fragments convert directly into PV A-fragments (bf16x2 pack) — no
// smem staging. PV B-frags via ldmatrix.x4.trans on the V tile.
// ---------------------------------------------------------------------------
#define TILE_BF16 (NTILE * HSTR)             // bf16 elems per tile = 2304
#define SMEM_BYTES (2 * 2 * TILE_BF16 * 2)   // K+V, 2 stages: 18432 B

__global__ __launch_bounds__(32 * NW) void attn_kernel(float* __restrict__ out)
{
    extern __shared__ __align__(16) __nv_bfloat16 sm[];
    __nv_bfloat16* smK = sm;                  // [2][NTILE][HSTR]
    __nv_bfloat16* smV = sm + 2 * TILE_BF16;  // [2][NTILE][HSTR]

    const int tid  = threadIdx.x;
    const int w    = tid >> 5;
    const int lane = tid & 31;
    const int gid  = lane >> 2;   // 0..7
    const int tig  = lane & 3;    // 0..3

    const int bh = blockIdx.y;
    const int b  = bh >> 4;
    const int h  = bh & 15;

    const __nv_bfloat16* Kg = g_K + (size_t)bh * Tdim * HD;
    const __nv_bfloat16* Vg = g_V + (size_t)bh * Tdim * HD;

    const uint32_t smK_base = (uint32_t)__cvta_generic_to_shared(smK);
    const uint32_t smV_base = (uint32_t)__cvta_generic_to_shared(smV);

    // cp.async mapping: chunk v (0..255): row = v>>3, c16 = v&7
    const int r0v = tid >> 3,          c0v = tid & 7;
    const int r1v = (tid + 128) >> 3,  c1v = (tid + 128) & 7;

    // ---- issue tile 0 ----
    cp_async16(smK_base + r0v * 144 + c0v * 16, Kg + r0v * HD + c0v * 8);
    cp_async16(smK_base + r1v * 144 + c1v * 16, Kg + r1v * HD + c1v * 8);
    cp_async16(smV_base + r0v * 144 + c0v * 16, Vg + r0v * HD + c0v * 8);
    cp_async16(smV_base + r1v * 144 + c1v * 16, Vg + r1v * HD + c1v * 8);
    cp_commit();

    // ---- Q fragments: two m16 tiles, bf16x2 regs ----
    const int qrow0 = blockIdx.x * MBLK + w * 32 + gid;
    uint32_t qf[2][4][4];
#pragma unroll
    for (int mt = 0; mt < 2; mt++) {
        const uint32_t* Qm =
            (const uint32_t*)(g_Q + ((size_t)bh * Tdim + qrow0 + mt * 16) * HD);
        const uint32_t* Qm8 = Qm + 8 * (HD / 2);
#pragma unroll
        for (int kt = 0; kt < 4; kt++) {
            qf[mt][kt][0] = Qm[8 * kt + tig];
            qf[mt][kt][1] = Qm8[8 * kt + tig];
            qf[mt][kt][2] = Qm[8 * kt + tig + 4];
            qf[mt][kt][3] = Qm8[8 * kt + tig + 4];
        }
    }

    float o[2][8][4];
#pragma unroll
    for (int mt = 0; mt < 2; mt++)
#pragma unroll
        for (int nt = 0; nt < 8; nt++)
#pragma unroll
            for (int i = 0; i < 4; i++) o[mt][nt][i] = 0.f;

    float mrow[2][2], lrow[2][2];
#pragma unroll
    for (int mt = 0; mt < 2; mt++) {
        mrow[mt][0] = -1e30f; mrow[mt][1] = -1e30f;
        lrow[mt][0] = 0.f;    lrow[mt][1] = 0.f;
    }

    // ldmatrix lane address components (V tile):
    // group g = lane>>3: g0=(k0,n0) g1=(k8,n0) g2=(k0,n8) g3=(k8,n8)
    const int lr = ((lane >> 3) & 1) * 8 + (lane & 7);  // row within 16-k block
    const int lc = (lane >> 4) * 8;                      // col within 16-n block

    for (int it = 0; it < NIT; it++) {
        const int st = it & 1;
        const uint32_t stK = smK_base + st * TILE_BF16 * 2;
        const uint32_t stV = smV_base + st * TILE_BF16 * 2;

        if (it + 1 < NIT) {
            const int ns = (it + 1) & 1;
            const __nv_bfloat16* Kn = Kg + (size_t)(it + 1) * NTILE * HD;
            const __nv_bfloat16* Vn = Vg + (size_t)(it + 1) * NTILE * HD;
            const uint32_t dK = smK_base + ns * TILE_BF16 * 2;
            const uint32_t dV = smV_base + ns * TILE_BF16 * 2;
            cp_async16(dK + r0v * 144 + c0v * 16, Kn + r0v * HD + c0v * 8);
            cp_async16(dK + r1v * 144 + c1v * 16, Kn + r1v * HD + c1v * 8);
            cp_async16(dV + r0v * 144 + c0v * 16, Vn + r0v * HD + c0v * 8);
            cp_async16(dV + r1v * 144 + c1v * 16, Vn + r1v * HD + c1v * 8);
        }
        cp_commit();
        cp_wait1();
        __syncthreads();

        const uint32_t* Kt =
            (const uint32_t*)(smK + st * TILE_BF16);

        // ---- S = Q K^T : 4 key n-tiles x 4 k16-tiles, shared B-frags ----
        float sc[2][4][4];
#pragma unroll
        for (int nt = 0; nt < 4; nt++) {
#pragma unroll
            for (int mt = 0; mt < 2; mt++)
#pragma unroll
                for (int i = 0; i < 4; i++) sc[mt][nt][i] = 0.f;
            const uint32_t* kr = Kt + (nt * 8 + gid) * HSTRU;
#pragma unroll
            for (int kt = 0; kt < 4; kt++) {
                uint32_t b0 = kr[8 * kt + tig];
                uint32_t b1 = kr[8 * kt + tig + 4];
                mma_bf16(sc[0][nt][0], sc[0][nt][1], sc[0][nt][2], sc[0][nt][3],
                         qf[0][kt][0], qf[0][kt][1], qf[0][kt][2], qf[0][kt][3],
                         b0, b1);
                mma_bf16(sc[1][nt][0], sc[1][nt][1], sc[1][nt][2], sc[1][nt][3],
                         qf[1][kt][0], qf[1][kt][1], qf[1][kt][2], qf[1][kt][3],
                         b0, b1);
            }
        }

        // ---- online softmax (exp2 domain); P packed into A-frags ----
        uint32_t pa[2][2][4];
#pragma unroll
        for (int mt = 0; mt < 2; mt++) {
            float rm0 = -1e30f, rm1 = -1e30f;
#pragma unroll
            for (int nt = 0; nt < 4; nt++) {
                rm0 = fmaxf(rm0, fmaxf(sc[mt][nt][0], sc[mt][nt][1]));
                rm1 = fmaxf(rm1, fmaxf(sc[mt][nt][2], sc[mt][nt][3]));
            }
            rm0 = fmaxf(rm0, __shfl_xor_sync(0xffffffffu, rm0, 1));
            rm0 = fmaxf(rm0, __shfl_xor_sync(0xffffffffu, rm0, 2));
            rm1 = fmaxf(rm1, __shfl_xor_sync(0xffffffffu, rm1, 1));
            rm1 = fmaxf(rm1, __shfl_xor_sync(0xffffffffu, rm1, 2));

            const float nm0 = fmaxf(mrow[mt][0], rm0);
            const float nm1 = fmaxf(mrow[mt][1], rm1);
            const float corr0 = ex2(mrow[mt][0] - nm0);
            const float corr1 = ex2(mrow[mt][1] - nm1);
            mrow[mt][0] = nm0; mrow[mt][1] = nm1;

            float ls0 = 0.f, ls1 = 0.f;
#pragma unroll
            for (int nt = 0; nt < 4; nt++) {
                float p0 = ex2(sc[mt][nt][0] - nm0);
                float p1 = ex2(sc[mt][nt][1] - nm0);
                float p2 = ex2(sc[mt][nt][2] - nm1);
                float p3 = ex2(sc[mt][nt][3] - nm1);
                ls0 += p0 + p1;
                ls1 += p2 + p3;
                sc[mt][nt][0] = p0; sc[mt][nt][1] = p1;
                sc[mt][nt][2] = p2; sc[mt][nt][3] = p3;
            }
            lrow[mt][0] = lrow[mt][0] * corr0 + ls0;
            lrow[mt][1] = lrow[mt][1] * corr1 + ls1;

#pragma unroll
            for (int nt = 0; nt < 8; nt++) {
                o[mt][nt][0] *= corr0; o[mt][nt][1] *= corr0;
                o[mt][nt][2] *= corr1; o[mt][nt][3] *= corr1;
            }

            // P A-fragments: kt2 in {0,1} covers keys 16*kt2..16*kt2+15
#pragma unroll
            for (int kt2 = 0; kt2 < 2; kt2++) {
                pa[mt][kt2][0] = bf16x2(sc[mt][2 * kt2][1],     sc[mt][2 * kt2][0]);
                pa[mt][kt2][1] = bf16x2(sc[mt][2 * kt2][3],     sc[mt][2 * kt2][2]);
                pa[mt][kt2][2] = bf16x2(sc[mt][2 * kt2 + 1][1], sc[mt][2 * kt2 + 1][0]);
                pa[mt][kt2][3] = bf16x2(sc[mt][2 * kt2 + 1][3], sc[mt][2 * kt2 + 1][2]);
            }
        }

        // ---- O += P V : B-frags via ldmatrix.x4.trans ----
#pragma unroll
        for (int kt2 = 0; kt2 < 2; kt2++) {
#pragma unroll
            for (int nh = 0; nh < 4; nh++) {   // 16-wide hd blocks
                uint32_t saddr = stV + (kt2 * 16 + lr) * 144 + (nh * 16 + lc) * 2;
                uint32_t v0, v1, v2, v3;
                ldsm_x4_trans(v0, v1, v2, v3, saddr);
                // v0,v1 = b0,b1 for nt=2nh ; v2,v3 for nt=2nh+1
                mma_bf16(o[0][2 * nh][0], o[0][2 * nh][1],
                         o[0][2 * nh][2], o[0][2 * nh][3],
                         pa[0][kt2][0], pa[0][kt2][1], pa[0][kt2][2], pa[0][kt2][3],
                         v0, v1);
                mma_bf16(o[1][2 * nh][0], o[1][2 * nh][1],
                         o[1][2 * nh][2], o[1][2 * nh][3],
                         pa[1][kt2][0], pa[1][kt2][1], pa[1][kt2][2], pa[1][kt2][3],
                         v0, v1);
                mma_bf16(o[0][2 * nh + 1][0], o[0][2 * nh + 1][1],
                         o[0][2 * nh + 1][2], o[0][2 * nh + 1][3],
                         pa[0][kt2][0], pa[0][kt2][1], pa[0][kt2][2], pa[0][kt2][3],
                         v2, v3);
                mma_bf16(o[1][2 * nh + 1][0], o[1][2 * nh + 1][1],
                         o[1][2 * nh + 1][2], o[1][2 * nh + 1][3],
                         pa[1][kt2][0], pa[1][kt2][1], pa[1][kt2][2], pa[1][kt2][3],
                         v2, v3);
            }
        }

        __syncthreads();
    }

    // ---- epilogue ----
#pragma unroll
    for (int mt = 0; mt < 2; mt++) {
        float l0 = lrow[mt][0], l1 = lrow[mt][1];
        l0 += __shfl_xor_sync(0xffffffffu, l0, 1);
        l0 += __shfl_xor_sync(0xffffffffu, l0, 2);
        l1 += __shfl_xor_sync(0xffffffffu, l1, 1);
        l1 += __shfl_xor_sync(0xffffffffu, l1, 2);
        const float inv0 = 1.f / l0;
        const float inv1 = 1.f / l1;

        float* orow0 = out + ((size_t)(b * Tdim + qrow0 + mt * 16)) * Edim + h * HD;
        float* orow1 = orow0 + 8 * (size_t)Edim;
#pragma unroll
        for (int nt = 0; nt < 8; nt++) {
            float2* d0 = (float2*)&orow0[nt * 8 + 2 * tig];
            float2* d1 = (float2*)&orow1[nt * 8 + 2 * tig];
            *d0 = make_float2(o[mt][nt][0] * inv0, o[mt][nt][1] * inv0);
            *d1 = make_float2(o[mt][nt][2] * inv1, o[mt][nt][3] * inv1);
        }
    }
}

// ---------------------------------------------------------------------------
extern "C" void kernel_launch(void* const* d_in, const int* in_sizes, int n_in,
                              void* d_out, int out_size)
{
    const float* x    = (const float*)d_in[0];   // [2, 2048, 1024]
    const float* W    = (const float*)d_in[1];   // [64, 192]
    const float* bias = (const float*)d_in[2];   // [192]
    float* out = (float*)d_out;                  // [2, 2048, 1024]

    qkv_proj_kernel<<<Bdim * Tdim / TPB, QKV3>>>(x, W, bias);

    cudaFuncSetAttribute(attn_kernel,
                         cudaFuncAttributeMaxDynamicSharedMemorySize,
                         SMEM_BYTES);
    dim3 grid(Tdim / MBLK, Bdim * Hdim);   // 16 x 32 = 512 blocks
    attn_kernel<<<grid, 32 * NW, SMEM_BYTES>>>(out);
}

// round 11
// speedup vs baseline: 4.3613x; 1.4422x over previous
#include <cuda_runtime.h>
#include <cuda_fp16.h>
#include <cstdint>

#define Bdim 2
#define Tdim 2048
#define Edim 1024
#define Hdim 16
#define HD 64
#define QKV3 192
#define TPB 8              // (b,t) rows per QKV block

// Attention tiling
#define NW 2               // warps per block
#define MBLK 64            // queries per block (32 per warp: two m16 tiles)
#define NTILE 32           // keys per iteration
#define NIT (Tdim / NTILE) // 64
#define HSTR 72            // smem row stride in fp16 elems (144 B)
#define HSTRU 36           // ... in u32 units

#define LOG2E 1.4426950408889634f

// Scratch: Q/K/V in [B, H, T, HD] layout, fp16.
// Q pre-scaled by 0.125*log2(e) (softmax in exp2 domain).
__device__ __half g_Q[Bdim * Hdim * Tdim * HD];
__device__ __half g_K[Bdim * Hdim * Tdim * HD];
__device__ __half g_V[Bdim * Hdim * Tdim * HD];

typedef unsigned long long ull;

// ---------------------------------------------------------------------------
// helpers
// ---------------------------------------------------------------------------
__device__ __forceinline__ ull fma2(ull a, ull b, ull c) {
    ull d;
    asm("fma.rn.f32x2 %0, %1, %2, %3;" : "=l"(d) : "l"(a), "l"(b), "l"(c));
    return d;
}
__device__ __forceinline__ ull pack2(float lo, float hi) {
    ull r;
    asm("mov.b64 %0, {%1, %2};" : "=l"(r) : "f"(lo), "f"(hi));
    return r;
}
__device__ __forceinline__ float hadd2(ull v) {
    float lo, hi;
    asm("mov.b64 {%0, %1}, %2;" : "=f"(lo), "=f"(hi) : "l"(v));
    return lo + hi;
}
__device__ __forceinline__ float ex2(float x) {
    float y;
    asm("ex2.approx.ftz.f32 %0, %1;" : "=f"(y) : "f"(x));
    return y;
}
// d = {lo in lower half, hi in upper half} packed f16x2
__device__ __forceinline__ uint32_t f16x2(float hi, float lo) {
    uint32_t d;
    asm("cvt.rn.f16x2.f32 %0, %1, %2;" : "=r"(d) : "f"(hi), "f"(lo));
    return d;
}
__device__ __forceinline__ void mma_f16(
    float& c0, float& c1, float& c2, float& c3,
    uint32_t a0, uint32_t a1, uint32_t a2, uint32_t a3,
    uint32_t b0, uint32_t b1)
{
    asm volatile(
        "mma.sync.aligned.m16n8k16.row.col.f32.f16.f16.f32 "
        "{%0,%1,%2,%3}, {%4,%5,%6,%7}, {%8,%9}, {%0,%1,%2,%3};"
        : "+f"(c0), "+f"(c1), "+f"(c2), "+f"(c3)
        : "r"(a0), "r"(a1), "r"(a2), "r"(a3), "r"(b0), "r"(b1));
}
__device__ __forceinline__ void ldsm_x4_trans(
    uint32_t& r0, uint32_t& r1, uint32_t& r2, uint32_t& r3, uint32_t saddr)
{
    asm volatile(
        "ldmatrix.sync.aligned.m8n8.x4.trans.shared.b16 {%0,%1,%2,%3}, [%4];"
        : "=r"(r0), "=r"(r1), "=r"(r2), "=r"(r3) : "r"(saddr));
}
__device__ __forceinline__ void cp_async16(uint32_t smem_dst, const void* gmem_src) {
    asm volatile("cp.async.cg.shared.global [%0], [%1], 16;"
                 :: "r"(smem_dst), "l"(gmem_src) : "memory");
}
__device__ __forceinline__ void cp_commit() {
    asm volatile("cp.async.commit_group;" ::: "memory");
}
__device__ __forceinline__ void cp_wait1() {
    asm volatile("cp.async.wait_group 1;" ::: "memory");
}

// ---------------------------------------------------------------------------
// Kernel 1: QKV projection, fp32 math (f32x2), fp16 outputs.
// 8 (b,t) rows per block to amortize W register loads.
// ---------------------------------------------------------------------------
__global__ __launch_bounds__(QKV3) void qkv_proj_kernel(
    const float* __restrict__ x,      // [B, T, E]
    const float* __restrict__ W,      // [HD, 3*HD]
    const float* __restrict__ bias)   // [3*HD]
{
    __shared__ __align__(16) float xs[TPB * Edim];
    const int bt0 = blockIdx.x * TPB;

    const float* xsrc = x + (size_t)bt0 * Edim;
    for (int i = threadIdx.x; i < TPB * Edim; i += QKV3) xs[i] = xsrc[i];
    __syncthreads();

    const int d = threadIdx.x;  // 0..191

    ull w2[HD / 2];
#pragma unroll 8
    for (int k2 = 0; k2 < HD / 2; k2++)
        w2[k2] = pack2(W[(2 * k2) * QKV3 + d], W[(2 * k2 + 1) * QKV3 + d]);

    const float bv = bias[d];

#pragma unroll
    for (int r = 0; r < TPB; r++) {
        const int bt = bt0 + r;
        const int b  = bt / Tdim;
        const int t  = bt % Tdim;
        const ull* xs2 = (const ull*)(xs + r * Edim);

        float acc[Hdim];
#pragma unroll
        for (int h = 0; h < Hdim; h++) {
            ull a0 = 0ULL, a1 = 0ULL;
#pragma unroll
            for (int k2 = 0; k2 < HD / 2; k2 += 2) {
                a0 = fma2(xs2[h * (HD / 2) + k2],     w2[k2],     a0);
                a1 = fma2(xs2[h * (HD / 2) + k2 + 1], w2[k2 + 1], a1);
            }
            acc[h] = bv + (hadd2(a0) + hadd2(a1));
        }

#pragma unroll
        for (int h = 0; h < Hdim; h++) {
            const size_t off = ((size_t)(b * Hdim + h) * Tdim + t) * HD;
            if (d < HD) {
                g_Q[off + d] = __float2half(acc[h] * (0.125f * LOG2E));
            } else if (d < 2 * HD) {
                g_K[off + d - HD] = __float2half(acc[h]);
            } else {
                g_V[off + d - 2 * HD] = __float2half(acc[h]);
            }
        }
    }
}

// ---------------------------------------------------------------------------
// Kernel 2: fp16 tensor-core flash attention, m32 per warp, register P.
// 2 warps per block (64 queries) -> 1024 blocks, max phase diversity.
// S C-fragments convert directly into PV A-fragments (f16x2 pack).
// PV B-frags via ldmatrix.x4.trans on the V tile.
// ---------------------------------------------------------------------------
#define TILE_H (NTILE * HSTR)                // fp16 elems per tile = 2304
#define SMEM_BYTES (2 * 2 * TILE_H * 2)      // K+V, 2 stages: 18432 B

__global__ __launch_bounds__(32 * NW) void attn_kernel(float* __restrict__ out)
{
    extern __shared__ __align__(16) __half sm[];
    __half* smK = sm;               // [2][NTILE][HSTR]
    __half* smV = sm + 2 * TILE_H;  // [2][NTILE][HSTR]

    const int tid  = threadIdx.x;
    const int w    = tid >> 5;
    const int lane = tid & 31;
    const int gid  = lane >> 2;   // 0..7
    const int tig  = lane & 3;    // 0..3

    const int bh = blockIdx.y;
    const int b  = bh >> 4;
    const int h  = bh & 15;

    const __half* Kg = g_K + (size_t)bh * Tdim * HD;
    const __half* Vg = g_V + (size_t)bh * Tdim * HD;

    const uint32_t smK_base = (uint32_t)__cvta_generic_to_shared(smK);
    const uint32_t smV_base = (uint32_t)__cvta_generic_to_shared(smV);

    // cp.async mapping: 256 16B-chunks per array per tile, 64 threads -> 4 each.
    // chunk v: row = v>>3 (0..31), c16 = v&7 (0..7)
    int cprow[4], cpcol[4];
#pragma unroll
    for (int i = 0; i < 4; i++) {
        int v = tid + 64 * i;
        cprow[i] = v >> 3;
        cpcol[i] = v & 7;
    }

    // ---- issue tile 0 ----
#pragma unroll
    for (int i = 0; i < 4; i++) {
        cp_async16(smK_base + cprow[i] * 144 + cpcol[i] * 16,
                   Kg + cprow[i] * HD + cpcol[i] * 8);
        cp_async16(smV_base + cprow[i] * 144 + cpcol[i] * 16,
                   Vg + cprow[i] * HD + cpcol[i] * 8);
    }
    cp_commit();

    // ---- Q fragments: two m16 tiles, f16x2 regs ----
    const int qrow0 = blockIdx.x * MBLK + w * 32 + gid;
    uint32_t qf[2][4][4];
#pragma unroll
    for (int mt = 0; mt < 2; mt++) {
        const uint32_t* Qm =
            (const uint32_t*)(g_Q + ((size_t)bh * Tdim + qrow0 + mt * 16) * HD);
        const uint32_t* Qm8 = Qm + 8 * (HD / 2);
#pragma unroll
        for (int kt = 0; kt < 4; kt++) {
            qf[mt][kt][0] = Qm[8 * kt + tig];
            qf[mt][kt][1] = Qm8[8 * kt + tig];
            qf[mt][kt][2] = Qm[8 * kt + tig + 4];
            qf[mt][kt][3] = Qm8[8 * kt + tig + 4];
        }
    }

    float o[2][8][4];
#pragma unroll
    for (int mt = 0; mt < 2; mt++)
#pragma unroll
        for (int nt = 0; nt < 8; nt++)
#pragma unroll
            for (int i = 0; i < 4; i++) o[mt][nt][i] = 0.f;

    float mrow[2][2], lrow[2][2];
#pragma unroll
    for (int mt = 0; mt < 2; mt++) {
        mrow[mt][0] = -1e30f; mrow[mt][1] = -1e30f;
        lrow[mt][0] = 0.f;    lrow[mt][1] = 0.f;
    }

    // ldmatrix lane address components (V tile)
    const int lr = ((lane >> 3) & 1) * 8 + (lane & 7);  // row within 16-k block
    const int lc = (lane >> 4) * 8;                      // col within 16-n block

    for (int it = 0; it < NIT; it++) {
        const int st = it & 1;
        const uint32_t stV = smV_base + st * TILE_H * 2;

        if (it + 1 < NIT) {
            const int ns = (it + 1) & 1;
            const __half* Kn = Kg + (size_t)(it + 1) * NTILE * HD;
            const __half* Vn = Vg + (size_t)(it + 1) * NTILE * HD;
            const uint32_t dK = smK_base + ns * TILE_H * 2;
            const uint32_t dV = smV_base + ns * TILE_H * 2;
#pragma unroll
            for (int i = 0; i < 4; i++) {
                cp_async16(dK + cprow[i] * 144 + cpcol[i] * 16,
                           Kn + cprow[i] * HD + cpcol[i] * 8);
                cp_async16(dV + cprow[i] * 144 + cpcol[i] * 16,
                           Vn + cprow[i] * HD + cpcol[i] * 8);
            }
        }
        cp_commit();
        cp_wait1();
        __syncthreads();

        const uint32_t* Kt = (const uint32_t*)(smK + st * TILE_H);

        // ---- S = Q K^T : 4 key n-tiles x 4 k16-tiles, shared B-frags ----
        float sc[2][4][4];
#pragma unroll
        for (int nt = 0; nt < 4; nt++) {
#pragma unroll
            for (int mt = 0; mt < 2; mt++)
#pragma unroll
                for (int i = 0; i < 4; i++) sc[mt][nt][i] = 0.f;
            const uint32_t* kr = Kt + (nt * 8 + gid) * HSTRU;
#pragma unroll
            for (int kt = 0; kt < 4; kt++) {
                uint32_t b0 = kr[8 * kt + tig];
                uint32_t b1 = kr[8 * kt + tig + 4];
                mma_f16(sc[0][nt][0], sc[0][nt][1], sc[0][nt][2], sc[0][nt][3],
                        qf[0][kt][0], qf[0][kt][1], qf[0][kt][2], qf[0][kt][3],
                        b0, b1);
                mma_f16(sc[1][nt][0], sc[1][nt][1], sc[1][nt][2], sc[1][nt][3],
                        qf[1][kt][0], qf[1][kt][1], qf[1][kt][2], qf[1][kt][3],
                        b0, b1);
            }
        }

        // ---- online softmax (exp2 domain); P packed into A-frags ----
        uint32_t pa[2][2][4];
#pragma unroll
        for (int mt = 0; mt < 2; mt++) {
            float rm0 = -1e30f, rm1 = -1e30f;
#pragma unroll
            for (int nt = 0; nt < 4; nt++) {
                rm0 = fmaxf(rm0, fmaxf(sc[mt][nt][0], sc[mt][nt][1]));
                rm1 = fmaxf(rm1, fmaxf(sc[mt][nt][2], sc[mt][nt][3]));
            }
            rm0 = fmaxf(rm0, __shfl_xor_sync(0xffffffffu, rm0, 1));
            rm0 = fmaxf(rm0, __shfl_xor_sync(0xffffffffu, rm0, 2));
            rm1 = fmaxf(rm1, __shfl_xor_sync(0xffffffffu, rm1, 1));
            rm1 = fmaxf(rm1, __shfl_xor_sync(0xffffffffu, rm1, 2));

            const float nm0 = fmaxf(mrow[mt][0], rm0);
            const float nm1 = fmaxf(mrow[mt][1], rm1);
            const float corr0 = ex2(mrow[mt][0] - nm0);
            const float corr1 = ex2(mrow[mt][1] - nm1);
            mrow[mt][0] = nm0; mrow[mt][1] = nm1;

            float ls0 = 0.f, ls1 = 0.f;
#pragma unroll
            for (int nt = 0; nt < 4; nt++) {
                float p0 = ex2(sc[mt][nt][0] - nm0);
                float p1 = ex2(sc[mt][nt][1] - nm0);
                float p2 = ex2(sc[mt][nt][2] - nm1);
                float p3 = ex2(sc[mt][nt][3] - nm1);
                ls0 += p0 + p1;
                ls1 += p2 + p3;
                sc[mt][nt][0] = p0; sc[mt][nt][1] = p1;
                sc[mt][nt][2] = p2; sc[mt][nt][3] = p3;
            }
            lrow[mt][0] = lrow[mt][0] * corr0 + ls0;
            lrow[mt][1] = lrow[mt][1] * corr1 + ls1;

#pragma unroll
            for (int nt = 0; nt < 8; nt++) {
                o[mt][nt][0] *= corr0; o[mt][nt][1] *= corr0;
                o[mt][nt][2] *= corr1; o[mt][nt][3] *= corr1;
            }

            // P A-fragments: kt2 in {0,1} covers keys 16*kt2..16*kt2+15
#pragma unroll
            for (int kt2 = 0; kt2 < 2; kt2++) {
                pa[mt][kt2][0] = f16x2(sc[mt][2 * kt2][1],     sc[mt][2 * kt2][0]);
                pa[mt][kt2][1] = f16x2(sc[mt][2 * kt2][3],     sc[mt][2 * kt2][2]);
                pa[mt][kt2][2] = f16x2(sc[mt][2 * kt2 + 1][1], sc[mt][2 * kt2 + 1][0]);
                pa[mt][kt2][3] = f16x2(sc[mt][2 * kt2 + 1][3], sc[mt][2 * kt2 + 1][2]);
            }
        }

        // ---- O += P V : B-frags via ldmatrix.x4.trans ----
#pragma unroll
        for (int kt2 = 0; kt2 < 2; kt2++) {
#pragma unroll
            for (int nh = 0; nh < 4; nh++) {   // 16-wide hd blocks
                uint32_t saddr = stV + (kt2 * 16 + lr) * 144 + (nh * 16 + lc) * 2;
                uint32_t v0, v1, v2, v3;
                ldsm_x4_trans(v0, v1, v2, v3, saddr);
                mma_f16(o[0][2 * nh][0], o[0][2 * nh][1],
                        o[0][2 * nh][2], o[0][2 * nh][3],
                        pa[0][kt2][0], pa[0][kt2][1], pa[0][kt2][2], pa[0][kt2][3],
                        v0, v1);
                mma_f16(o[1][2 * nh][0], o[1][2 * nh][1],
                        o[1][2 * nh][2], o[1][2 * nh][3],
                        pa[1][kt2][0], pa[1][kt2][1], pa[1][kt2][2], pa[1][kt2][3],
                        v0, v1);
                mma_f16(o[0][2 * nh + 1][0], o[0][2 * nh + 1][1],
                        o[0][2 * nh + 1][2], o[0][2 * nh + 1][3],
                        pa[0][kt2][0], pa[0][kt2][1], pa[0][kt2][2], pa[0][kt2][3],
                        v2, v3);
                mma_f16(o[1][2 * nh + 1][0], o[1][2 * nh + 1][1],
                        o[1][2 * nh + 1][2], o[1][2 * nh + 1][3],
                        pa[1][kt2][0], pa[1][kt2][1], pa[1][kt2][2], pa[1][kt2][3],
                        v2, v3);
            }
        }

        __syncthreads();
    }

    // ---- epilogue ----
#pragma unroll
    for (int mt = 0; mt < 2; mt++) {
        float l0 = lrow[mt][0], l1 = lrow[mt][1];
        l0 += __shfl_xor_sync(0xffffffffu, l0, 1);
        l0 += __shfl_xor_sync(0xffffffffu, l0, 2);
        l1 += __shfl_xor_sync(0xffffffffu, l1, 1);
        l1 += __shfl_xor_sync(0xffffffffu, l1, 2);
        const float inv0 = 1.f / l0;
        const float inv1 = 1.f / l1;

        float* orow0 = out + ((size_t)(b * Tdim + qrow0 + mt * 16)) * Edim + h * HD;
        float* orow1 = orow0 + 8 * (size_t)Edim;
#pragma unroll
        for (int nt = 0; nt < 8; nt++) {
            float2* d0 = (float2*)&orow0[nt * 8 + 2 * tig];
            float2* d1 = (float2*)&orow1[nt * 8 + 2 * tig];
            *d0 = make_float2(o[mt][nt][0] * inv0, o[mt][nt][1] * inv0);
            *d1 = make_float2(o[mt][nt][2] * inv1, o[mt][nt][3] * inv1);
        }
    }
}

// ---------------------------------------------------------------------------
extern "C" void kernel_launch(void* const* d_in, const int* in_sizes, int n_in,
                              void* d_out, int out_size)
{
    const float* x    = (const float*)d_in[0];   // [2, 2048, 1024]
    const float* W    = (const float*)d_in[1];   // [64, 192]
    const float* bias = (const float*)d_in[2];   // [192]
    float* out = (float*)d_out;                  // [2, 2048, 1024]

    qkv_proj_kernel<<<Bdim * Tdim / TPB, QKV3>>>(x, W, bias);

    cudaFuncSetAttribute(attn_kernel,
                         cudaFuncAttributeMaxDynamicSharedMemorySize,
                         SMEM_BYTES);
    dim3 grid(Tdim / MBLK, Bdim * Hdim);   // 32 x 32 = 1024 blocks
    attn_kernel<<<grid, 32 * NW, SMEM_BYTES>>>(out);
}

// round 12
// speedup vs baseline: 7.6480x; 1.7536x over previous
#include <cuda_runtime.h>
#include <cuda_fp16.h>
#include <cstdint>

#define Bdim 2
#define Tdim 2048
#define Edim 1024
#define Hdim 16
#define HD 64
#define QKV3 192

// Attention tiling
#define NW 2               // warps per block
#define MBLK 64            // queries per block (32 per warp)
#define NTILE 64           // keys per iteration
#define NIT (Tdim / NTILE) // 32
#define HSTR 72            // smem row stride in fp16 elems (144 B)
#define HSTRU 36           // ... in u32 units

// QKV GEMM tiling
#define QTHREADS 128
#define MROWS 128          // (b,t) rows per block
#define XSTR 72            // x smem stride (halfs)
#define WSTR 200           // W smem stride (halfs)

#define LOG2E 1.4426950408889634f
#define QSCALE (0.125f * LOG2E)

// Scratch: Q/K/V in [B, H, T, HD] layout, fp16.
// Q pre-scaled by 0.125*log2(e) (softmax in exp2 domain).
__device__ __half g_Q[Bdim * Hdim * Tdim * HD];
__device__ __half g_K[Bdim * Hdim * Tdim * HD];
__device__ __half g_V[Bdim * Hdim * Tdim * HD];

// ---------------------------------------------------------------------------
// helpers
// ---------------------------------------------------------------------------
__device__ __forceinline__ float ex2(float x) {
    float y;
    asm("ex2.approx.ftz.f32 %0, %1;" : "=f"(y) : "f"(x));
    return y;
}
// d = {lo in lower half, hi in upper half} packed f16x2
__device__ __forceinline__ uint32_t f16x2(float hi, float lo) {
    uint32_t d;
    asm("cvt.rn.f16x2.f32 %0, %1, %2;" : "=r"(d) : "f"(hi), "f"(lo));
    return d;
}
__device__ __forceinline__ void mma_f16(
    float& c0, float& c1, float& c2, float& c3,
    uint32_t a0, uint32_t a1, uint32_t a2, uint32_t a3,
    uint32_t b0, uint32_t b1)
{
    asm volatile(
        "mma.sync.aligned.m16n8k16.row.col.f32.f16.f16.f32 "
        "{%0,%1,%2,%3}, {%4,%5,%6,%7}, {%8,%9}, {%0,%1,%2,%3};"
        : "+f"(c0), "+f"(c1), "+f"(c2), "+f"(c3)
        : "r"(a0), "r"(a1), "r"(a2), "r"(a3), "r"(b0), "r"(b1));
}
__device__ __forceinline__ void ldsm_x4(
    uint32_t& r0, uint32_t& r1, uint32_t& r2, uint32_t& r3, uint32_t saddr)
{
    asm volatile(
        "ldmatrix.sync.aligned.m8n8.x4.shared.b16 {%0,%1,%2,%3}, [%4];"
        : "=r"(r0), "=r"(r1), "=r"(r2), "=r"(r3) : "r"(saddr));
}
__device__ __forceinline__ void ldsm_x4_trans(
    uint32_t& r0, uint32_t& r1, uint32_t& r2, uint32_t& r3, uint32_t saddr)
{
    asm volatile(
        "ldmatrix.sync.aligned.m8n8.x4.trans.shared.b16 {%0,%1,%2,%3}, [%4];"
        : "=r"(r0), "=r"(r1), "=r"(r2), "=r"(r3) : "r"(saddr));
}
__device__ __forceinline__ void cp_async16(uint32_t smem_dst, const void* gmem_src) {
    asm volatile("cp.async.cg.shared.global [%0], [%1], 16;"
                 :: "r"(smem_dst), "l"(gmem_src) : "memory");
}
__device__ __forceinline__ void cp_commit() {
    asm volatile("cp.async.commit_group;" ::: "memory");
}
__device__ __forceinline__ void cp_wait1() {
    asm volatile("cp.async.wait_group 1;" ::: "memory");
}

// ---------------------------------------------------------------------------
// Kernel 1: QKV projection as an fp16 tensor-core GEMM.
// A = x viewed as [(h, b, t), 64] fp16, B = W [64, 192] fp16, C += bias.
// Block: (128 bt-rows, 1 head), 4 warps; warp w owns n-columns 48w..48w+47
// (6 n-tiles). B-frags via ldmatrix.x4.trans (same pattern as attn PV).
// ---------------------------------------------------------------------------
__global__ __launch_bounds__(QTHREADS) void qkv_mma_kernel(
    const float* __restrict__ x,      // [B, T, E]
    const float* __restrict__ W,      // [64, 192]
    const float* __restrict__ bias)   // [192]
{
    __shared__ __align__(16) __half xA[MROWS * XSTR];  // 18432 B
    __shared__ __align__(16) __half Wk[64 * WSTR];     // 25600 B

    const int tid  = threadIdx.x;
    const int w    = tid >> 5;
    const int lane = tid & 31;
    const int gid  = lane >> 2;
    const int tig  = lane & 3;

    const int bt0 = blockIdx.x * MROWS;
    const int h   = blockIdx.y;
    const int b   = bt0 >> 11;          // 2048 t-rows per batch
    const int t0  = bt0 & 2047;

    // ---- load x tile (fp32 -> fp16), rows bt0..bt0+127, cols h*64..+63 ----
#pragma unroll
    for (int i = 0; i < 16; i++) {
        int idx = tid + QTHREADS * i;   // 0..2047 float4 chunks
        int r = idx >> 4, c4 = (idx & 15) * 4;
        float4 v = *(const float4*)(x + (size_t)(bt0 + r) * Edim + h * HD + c4);
        __half2* dst = (__half2*)(xA + r * XSTR + c4);
        dst[0] = __floats2half2_rn(v.x, v.y);
        dst[1] = __floats2half2_rn(v.z, v.w);
    }
    // ---- load W (fp32 -> fp16), [64][192] ----
#pragma unroll
    for (int i = 0; i < 24; i++) {
        int idx = tid + QTHREADS * i;   // 0..3071 float4 chunks
        int k = idx / 48, c4 = (idx % 48) * 4;
        float4 v = *(const float4*)(W + k * QKV3 + c4);
        __half2* dst = (__half2*)(Wk + k * WSTR + c4);
        dst[0] = __floats2half2_rn(v.x, v.y);
        dst[1] = __floats2half2_rn(v.z, v.w);
    }
    __syncthreads();

    const uint32_t xA_base = (uint32_t)__cvta_generic_to_shared(xA);
    const uint32_t Wk_base = (uint32_t)__cvta_generic_to_shared(Wk);

    const int lr = ((lane >> 3) & 1) * 8 + (lane & 7);
    const int lc = (lane >> 4) * 8;

    // ---- B fragments: 6 n-tiles x 4 k16-steps ----
    uint32_t bf[4][6][2];
#pragma unroll
    for (int kt = 0; kt < 4; kt++)
#pragma unroll
        for (int nb = 0; nb < 3; nb++) {
            uint32_t saddr = Wk_base + (kt * 16 + lr) * (WSTR * 2)
                           + (w * 48 + nb * 16 + lc) * 2;
            ldsm_x4_trans(bf[kt][2 * nb][0], bf[kt][2 * nb][1],
                          bf[kt][2 * nb + 1][0], bf[kt][2 * nb + 1][1], saddr);
        }

    // ---- per-n-tile bias, scale, destination ----
    float bx[6], by[6], scl[6];
    __half* dbase[6];
#pragma unroll
    for (int nt = 0; nt < 6; nt++) {
        int n = w * 48 + nt * 8 + 2 * tig;
        bx[nt] = bias[n];
        by[nt] = bias[n + 1];
        int g = 6 * w + nt;             // global n-tile 0..23
        int part = g >> 3;              // 0=Q 1=K 2=V
        scl[nt] = (part == 0) ? QSCALE : 1.f;
        __half* base = (part == 0) ? g_Q : (part == 1) ? g_K : g_V;
        // column offset within the part + head row base
        dbase[nt] = base + ((size_t)(b * Hdim + h) * Tdim) * HD
                  + (g & 7) * 8 + 2 * tig;
    }

    // ---- m-loop: 8 m16 tiles ----
#pragma unroll
    for (int mt = 0; mt < 8; mt++) {
        uint32_t af[4][4];
#pragma unroll
        for (int kt = 0; kt < 4; kt++) {
            uint32_t saddr = xA_base + (mt * 16 + (lane & 15)) * (XSTR * 2)
                           + kt * 32 + (lane >> 4) * 16;
            ldsm_x4(af[kt][0], af[kt][1], af[kt][2], af[kt][3], saddr);
        }
        const int t = t0 + mt * 16 + gid;
#pragma unroll
        for (int nt = 0; nt < 6; nt++) {
            float c0 = 0.f, c1 = 0.f, c2 = 0.f, c3 = 0.f;
#pragma unroll
            for (int kt = 0; kt < 4; kt++)
                mma_f16(c0, c1, c2, c3,
                        af[kt][0], af[kt][1], af[kt][2], af[kt][3],
                        bf[kt][nt][0], bf[kt][nt][1]);
            c0 = (c0 + bx[nt]) * scl[nt];
            c1 = (c1 + by[nt]) * scl[nt];
            c2 = (c2 + bx[nt]) * scl[nt];
            c3 = (c3 + by[nt]) * scl[nt];
            *(__half2*)(dbase[nt] + (size_t)t * HD)       = __floats2half2_rn(c0, c1);
            *(__half2*)(dbase[nt] + (size_t)(t + 8) * HD) = __floats2half2_rn(c2, c3);
        }
    }
}

// ---------------------------------------------------------------------------
// Kernel 2: fp16 tensor-core flash attention, m32 per warp, register P.
// NTILE=64 keys per iteration (halved per-key softmax fixed costs).
// ---------------------------------------------------------------------------
#define TILE_H (NTILE * HSTR)                // fp16 elems per tile = 4608
#define SMEM_BYTES (2 * 2 * TILE_H * 2)      // K+V, 2 stages: 36864 B

__global__ __launch_bounds__(32 * NW) void attn_kernel(float* __restrict__ out)
{
    extern __shared__ __align__(16) __half sm[];
    __half* smK = sm;               // [2][NTILE][HSTR]
    __half* smV = sm + 2 * TILE_H;  // [2][NTILE][HSTR]

    const int tid  = threadIdx.x;
    const int w    = tid >> 5;
    const int lane = tid & 31;
    const int gid  = lane >> 2;
    const int tig  = lane & 3;

    const int bh = blockIdx.y;
    const int b  = bh >> 4;
    const int h  = bh & 15;

    const __half* Kg = g_K + (size_t)bh * Tdim * HD;
    const __half* Vg = g_V + (size_t)bh * Tdim * HD;

    const uint32_t smK_base = (uint32_t)__cvta_generic_to_shared(smK);
    const uint32_t smV_base = (uint32_t)__cvta_generic_to_shared(smV);

    // cp.async mapping: 512 16B-chunks per array per tile, 64 threads -> 8 each
    int cprow[8], cpcol[8];
#pragma unroll
    for (int i = 0; i < 8; i++) {
        int v = tid + 64 * i;
        cprow[i] = v >> 3;
        cpcol[i] = v & 7;
    }

    // ---- issue tile 0 ----
#pragma unroll
    for (int i = 0; i < 8; i++) {
        cp_async16(smK_base + cprow[i] * 144 + cpcol[i] * 16,
                   Kg + cprow[i] * HD + cpcol[i] * 8);
        cp_async16(smV_base + cprow[i] * 144 + cpcol[i] * 16,
                   Vg + cprow[i] * HD + cpcol[i] * 8);
    }
    cp_commit();

    // ---- Q fragments: two m16 tiles ----
    const int qrow0 = blockIdx.x * MBLK + w * 32 + gid;
    uint32_t qf[2][4][4];
#pragma unroll
    for (int mt = 0; mt < 2; mt++) {
        const uint32_t* Qm =
            (const uint32_t*)(g_Q + ((size_t)bh * Tdim + qrow0 + mt * 16) * HD);
        const uint32_t* Qm8 = Qm + 8 * (HD / 2);
#pragma unroll
        for (int kt = 0; kt < 4; kt++) {
            qf[mt][kt][0] = Qm[8 * kt + tig];
            qf[mt][kt][1] = Qm8[8 * kt + tig];
            qf[mt][kt][2] = Qm[8 * kt + tig + 4];
            qf[mt][kt][3] = Qm8[8 * kt + tig + 4];
        }
    }

    float o[2][8][4];
#pragma unroll
    for (int mt = 0; mt < 2; mt++)
#pragma unroll
        for (int nt = 0; nt < 8; nt++)
#pragma unroll
            for (int i = 0; i < 4; i++) o[mt][nt][i] = 0.f;

    float mrow[2][2], lrow[2][2];
#pragma unroll
    for (int mt = 0; mt < 2; mt++) {
        mrow[mt][0] = -1e30f; mrow[mt][1] = -1e30f;
        lrow[mt][0] = 0.f;    lrow[mt][1] = 0.f;
    }

    const int lr = ((lane >> 3) & 1) * 8 + (lane & 7);
    const int lc = (lane >> 4) * 8;

    for (int it = 0; it < NIT; it++) {
        const int st = it & 1;
        const uint32_t stV = smV_base + st * TILE_H * 2;

        if (it + 1 < NIT) {
            const int ns = (it + 1) & 1;
            const __half* Kn = Kg + (size_t)(it + 1) * NTILE * HD;
            const __half* Vn = Vg + (size_t)(it + 1) * NTILE * HD;
            const uint32_t dK = smK_base + ns * TILE_H * 2;
            const uint32_t dV = smV_base + ns * TILE_H * 2;
#pragma unroll
            for (int i = 0; i < 8; i++) {
                cp_async16(dK + cprow[i] * 144 + cpcol[i] * 16,
                           Kn + cprow[i] * HD + cpcol[i] * 8);
                cp_async16(dV + cprow[i] * 144 + cpcol[i] * 16,
                           Vn + cprow[i] * HD + cpcol[i] * 8);
            }
        }
        cp_commit();
        cp_wait1();
        __syncthreads();

        const uint32_t* Kt = (const uint32_t*)(smK + st * TILE_H);

        // ---- S = Q K^T : 8 key n-tiles x 4 k16-tiles, shared B-frags ----
        float sc[2][8][4];
#pragma unroll
        for (int nt = 0; nt < 8; nt++) {
#pragma unroll
            for (int mt = 0; mt < 2; mt++)
#pragma unroll
                for (int i = 0; i < 4; i++) sc[mt][nt][i] = 0.f;
            const uint32_t* kr = Kt + (nt * 8 + gid) * HSTRU;
#pragma unroll
            for (int kt = 0; kt < 4; kt++) {
                uint32_t b0 = kr[8 * kt + tig];
                uint32_t b1 = kr[8 * kt + tig + 4];
                mma_f16(sc[0][nt][0], sc[0][nt][1], sc[0][nt][2], sc[0][nt][3],
                        qf[0][kt][0], qf[0][kt][1], qf[0][kt][2], qf[0][kt][3],
                        b0, b1);
                mma_f16(sc[1][nt][0], sc[1][nt][1], sc[1][nt][2], sc[1][nt][3],
                        qf[1][kt][0], qf[1][kt][1], qf[1][kt][2], qf[1][kt][3],
                        b0, b1);
            }
        }

        // ---- online softmax (exp2 domain); P packed into A-frags ----
        uint32_t pa[2][4][4];
#pragma unroll
        for (int mt = 0; mt < 2; mt++) {
            float rm0 = -1e30f, rm1 = -1e30f;
#pragma unroll
            for (int nt = 0; nt < 8; nt++) {
                rm0 = fmaxf(rm0, fmaxf(sc[mt][nt][0], sc[mt][nt][1]));
                rm1 = fmaxf(rm1, fmaxf(sc[mt][nt][2], sc[mt][nt][3]));
            }
            rm0 = fmaxf(rm0, __shfl_xor_sync(0xffffffffu, rm0, 1));
            rm0 = fmaxf(rm0, __shfl_xor_sync(0xffffffffu, rm0, 2));
            rm1 = fmaxf(rm1, __shfl_xor_sync(0xffffffffu, rm1, 1));
            rm1 = fmaxf(rm1, __shfl_xor_sync(0xffffffffu, rm1, 2));

            const float nm0 = fmaxf(mrow[mt][0], rm0);
            const float nm1 = fmaxf(mrow[mt][1], rm1);
            const float corr0 = ex2(mrow[mt][0] - nm0);
            const float corr1 = ex2(mrow[mt][1] - nm1);
            mrow[mt][0] = nm0; mrow[mt][1] = nm1;

            float ls0 = 0.f, ls1 = 0.f;
#pragma unroll
            for (int nt = 0; nt < 8; nt++) {
                float p0 = ex2(sc[mt][nt][0] - nm0);
                float p1 = ex2(sc[mt][nt][1] - nm0);
                float p2 = ex2(sc[mt][nt][2] - nm1);
                float p3 = ex2(sc[mt][nt][3] - nm1);
                ls0 += p0 + p1;
                ls1 += p2 + p3;
                sc[mt][nt][0] = p0; sc[mt][nt][1] = p1;
                sc[mt][nt][2] = p2; sc[mt][nt][3] = p3;
            }
            lrow[mt][0] = lrow[mt][0] * corr0 + ls0;
            lrow[mt][1] = lrow[mt][1] * corr1 + ls1;

#pragma unroll
            for (int nt = 0; nt < 8; nt++) {
                o[mt][nt][0] *= corr0; o[mt][nt][1] *= corr0;
                o[mt][nt][2] *= corr1; o[mt][nt][3] *= corr1;
            }

#pragma unroll
            for (int kt2 = 0; kt2 < 4; kt2++) {
                pa[mt][kt2][0] = f16x2(sc[mt][2 * kt2][1],     sc[mt][2 * kt2][0]);
                pa[mt][kt2][1] = f16x2(sc[mt][2 * kt2][3],     sc[mt][2 * kt2][2]);
                pa[mt][kt2][2] = f16x2(sc[mt][2 * kt2 + 1][1], sc[mt][2 * kt2 + 1][0]);
                pa[mt][kt2][3] = f16x2(sc[mt][2 * kt2 + 1][3], sc[mt][2 * kt2 + 1][2]);
            }
        }

        // ---- O += P V : B-frags via ldmatrix.x4.trans ----
#pragma unroll
        for (int kt2 = 0; kt2 < 4; kt2++) {
#pragma unroll
            for (int nh = 0; nh < 4; nh++) {
                uint32_t saddr = stV + (kt2 * 16 + lr) * 144 + (nh * 16 + lc) * 2;
                uint32_t v0, v1, v2, v3;
                ldsm_x4_trans(v0, v1, v2, v3, saddr);
                mma_f16(o[0][2 * nh][0], o[0][2 * nh][1],
                        o[0][2 * nh][2], o[0][2 * nh][3],
                        pa[0][kt2][0], pa[0][kt2][1], pa[0][kt2][2], pa[0][kt2][3],
                        v0, v1);
                mma_f16(o[1][2 * nh][0], o[1][2 * nh][1],
                        o[1][2 * nh][2], o[1][2 * nh][3],
                        pa[1][kt2][0], pa[1][kt2][1], pa[1][kt2][2], pa[1][kt2][3],
                        v0, v1);
                mma_f16(o[0][2 * nh + 1][0], o[0][2 * nh + 1][1],
                        o[0][2 * nh + 1][2], o[0][2 * nh + 1][3],
                        pa[0][kt2][0], pa[0][kt2][1], pa[0][kt2][2], pa[0][kt2][3],
                        v2, v3);
                mma_f16(o[1][2 * nh + 1][0], o[1][2 * nh + 1][1],
                        o[1][2 * nh + 1][2], o[1][2 * nh + 1][3],
                        pa[1][kt2][0], pa[1][kt2][1], pa[1][kt2][2], pa[1][kt2][3],
                        v2, v3);
            }
        }

        __syncthreads();
    }

    // ---- epilogue ----
#pragma unroll
    for (int mt = 0; mt < 2; mt++) {
        float l0 = lrow[mt][0], l1 = lrow[mt][1];
        l0 += __shfl_xor_sync(0xffffffffu, l0, 1);
        l0 += __shfl_xor_sync(0xffffffffu, l0, 2);
        l1 += __shfl_xor_sync(0xffffffffu, l1, 1);
        l1 += __shfl_xor_sync(0xffffffffu, l1, 2);
        const float inv0 = 1.f / l0;
        const float inv1 = 1.f / l1;

        float* orow0 = out + ((size_t)(b * Tdim + qrow0 + mt * 16)) * Edim + h * HD;
        float* orow1 = orow0 + 8 * (size_t)Edim;
#pragma unroll
        for (int nt = 0; nt < 8; nt++) {
            float2* d0 = (float2*)&orow0[nt * 8 + 2 * tig];
            float2* d1 = (float2*)&orow1[nt * 8 + 2 * tig];
            *d0 = make_float2(o[mt][nt][0] * inv0, o[mt][nt][1] * inv0);
            *d1 = make_float2(o[mt][nt][2] * inv1, o[mt][nt][3] * inv1);
        }
    }
}

// ---------------------------------------------------------------------------
extern "C" void kernel_launch(void* const* d_in, const int* in_sizes, int n_in,
                              void* d_out, int out_size)
{
    const float* x    = (const float*)d_in[0];   // [2, 2048, 1024]
    const float* W    = (const float*)d_in[1];   // [64, 192]
    const float* bias = (const float*)d_in[2];   // [192]
    float* out = (float*)d_out;                  // [2, 2048, 1024]

    dim3 qgrid(Bdim * Tdim / MROWS, Hdim);       // 32 x 16 = 512 blocks
    qkv_mma_kernel<<<qgrid, QTHREADS>>>(x, W, bias);

    cudaFuncSetAttribute(attn_kernel,
                         cudaFuncAttributeMaxDynamicSharedMemorySize,
                         SMEM_BYTES);
    dim3 grid(Tdim / MBLK, Bdim * Hdim);         // 32 x 32 = 1024 blocks
    attn_kernel<<<grid, 32 * NW, SMEM_BYTES>>>(out);
}